// round 8
// baseline (speedup 1.0000x reference)
#include <cuda_runtime.h>
#include <cuda_fp16.h>
#include <math.h>

#define BB 4
#define NN 128
#define FF 128
#define SS 5
#define TGLOB 32
#define LL 2
#define TBL 512
#define LMAX 16.0f
#define TBL_SCALE (TBL / LMAX)
#define TBLK (TBL / 8)          /* table blocks per layer = 64 */

// ---------------- persistent scratch (device globals; no allocation) ------
__device__ float g_posbuf[2][BB * NN * 3];
__device__ float4 g_veczbuf[2][BB * NN * FF];     // (v0,v1,v2,z) per node-channel
__device__ float g_A4[BB * NN * 4 * FF];          // gated A for k=0..3
__device__ __half2 g_tblh[LL * TBL * 512];        // (w_t, w_{t+1}) pairs

// ---------------- fused prep: radial tables (half2 pairs) + embed/init ----
__global__ __launch_bounds__(128) void k_prep(const float* __restrict__ Wr1,
                                              const float* __restrict__ br1,
                                              const float* __restrict__ Wr2,
                                              const float* __restrict__ positions,
                                              const int* __restrict__ node_features,
                                              const float* __restrict__ gf,
                                              const float* __restrict__ W_embed,
                                              const float* __restrict__ b_embed,
                                              const float* __restrict__ Wnode) {
    const int c = threadIdx.x;
    if (blockIdx.x < TBLK * LL) {
        const int i = blockIdx.x / TBLK;
        const int tb0 = (blockIdx.x % TBLK) * 8;
        __shared__ float h[9][64];
        if (c < 64) {
            float w1 = Wr1[i * 64 + c];
            float b1 = br1[i * 64 + c];
#pragma unroll
            for (int j = 0; j < 9; j++) {
                float lng = (float)(tb0 + j) * (LMAX / (float)TBL);
                float p = lng * w1 + b1;
                h[j][c] = p / (1.0f + expf(-p));
            }
        }
        __syncthreads();
        const float* W = Wr2 + i * 64 * 512 + c;
        float acc[9][4];
#pragma unroll
        for (int j = 0; j < 9; j++)
#pragma unroll
            for (int d = 0; d < 4; d++) acc[j][d] = 0.f;
#pragma unroll 4
        for (int m = 0; m < 64; m++) {
            float w0 = W[m * 512 + 0];
            float w1v = W[m * 512 + 128];
            float w2 = W[m * 512 + 256];
            float w3 = W[m * 512 + 384];
#pragma unroll
            for (int j = 0; j < 9; j++) {
                float hm = h[j][m];
                acc[j][0] = fmaf(hm, w0, acc[j][0]);
                acc[j][1] = fmaf(hm, w1v, acc[j][1]);
                acc[j][2] = fmaf(hm, w2, acc[j][2]);
                acc[j][3] = fmaf(hm, w3, acc[j][3]);
            }
        }
#pragma unroll
        for (int j = 0; j < 8; j++) {
            __half2* dst = g_tblh + ((size_t)i * TBL + tb0 + j) * 512 + c * 4;
#pragma unroll
            for (int d = 0; d < 4; d++)
                dst[d] = __float22half2_rn(make_float2(acc[j][d], acc[j + 1][d]));
        }
    } else {
        const int bn = blockIdx.x - TBLK * LL;
        const int b = bn / NN;
        int nf = node_features[bn];
        float s = W_embed[(nf - 1) * FF + c] + b_embed[c];
#pragma unroll 8
        for (int t = 0; t < TGLOB; t++)
            s = fmaf(gf[b * TGLOB + t], W_embed[(SS + t) * FF + c], s);
        if (c < 3) g_posbuf[0][bn * 3 + c] = positions[bn * 3 + c];

        __shared__ float srow[FF];
        srow[c] = s;
        __syncthreads();
        float acc = 0.f;
#pragma unroll 8
        for (int k = 0; k < FF; k++)
            acc = fmaf(srow[k], Wnode[k * FF + c], acc);
        g_veczbuf[0][bn * FF + c] = make_float4(0.f, 0.f, 0.f, acc);
    }
}

// ---------------- message gather + gate --------------------------------
// grid (NN, BB, 2): z = channel half. blockDim (64,4): c in half, q = sender quarter.
__global__ __launch_bounds__(256, 4) void k_msg(const float* __restrict__ pos_in,
                                                const float* __restrict__ c1w,
                                                const float* __restrict__ c2w,
                                                const float* __restrict__ c3w,
                                                int layer) {
    const int r = blockIdx.x;
    const int b = blockIdx.y;
    const int ch = blockIdx.z * 64 + threadIdx.x;   // global channel
    const int q = threadIdx.y;
    const int tid = q * 64 + threadIdx.x;
    const int p = layer & 1;

    __shared__ float sp[NN * 3];
    __shared__ float sp0[NN * 3];
    __shared__ float4 sData[NN][5];
    __shared__ float red[3][16 * 64];

    for (int idx = tid; idx < NN * 3; idx += 256) {
        sp[idx]  = g_posbuf[p][b * NN * 3 + idx];
        sp0[idx] = pos_in[b * NN * 3 + idx];
    }
    __syncthreads();

    if (tid < NN) {
        const int s = tid;
        const float rx = sp[r * 3 + 0], ry = sp[r * 3 + 1], rz = sp[r * 3 + 2];
        float dx0 = sp0[r * 3 + 0] - sp0[s * 3 + 0];
        float dy0 = sp0[r * 3 + 1] - sp0[s * 3 + 1];
        float dz0 = sp0[r * 3 + 2] - sp0[s * 3 + 2];
        float l0 = sqrtf(dx0 * dx0 + dy0 * dy0 + dz0 * dz0 + 1e-12f);
        float env = (l0 < 10.0f) ? 0.5f * (cosf(l0 * 0.3141592653589793f) + 1.0f) : 0.0f;
        if (s == r) env = 0.0f;

        float vx = rx - sp[s * 3 + 0];
        float vy = ry - sp[s * 3 + 1];
        float vz = rz - sp[s * 3 + 2];
        float lng = sqrtf(vx * vx + vy * vy + vz * vz + 1e-12f);
        float inv = 1.0f / lng;
        float ux = vx * inv, uy = vy * inv, uz = vz * inv;

        const float s5 = 2.2360679774997896f,
                    s15 = 3.872983346207417f, s35_8 = 2.091650066335189f,
                    s105 = 10.246950765959598f, s21_8 = 1.6201851746019651f,
                    s7 = 2.6457513110645907f;
        float xx = ux * ux, yy = uy * uy, zz = uz * uz;
        float Y4 = s15 * ux * uy, Y5 = s15 * uy * uz;
        float Y6 = 0.5f * s5 * (3.f * zz - 1.f);
        float Y7 = s15 * ux * uz;
        float Y8 = 0.5f * s15 * (xx - yy);
        float Y9 = s35_8 * uy * (3.f * xx - yy);
        float Y10 = s105 * ux * uy * uz;
        float Y11 = s21_8 * uy * (5.f * zz - 1.f);
        float Y12 = 0.5f * s7 * uz * (5.f * zz - 3.f);
        float Y13 = s21_8 * ux * (5.f * zz - 1.f);
        float Y14 = 0.5f * s105 * uz * (xx - yy);
        float Y15 = s35_8 * ux * (xx - 3.f * yy);

        float tp = fminf(lng * TBL_SCALE, (float)TBL - 1.001f);
        int it = (int)tp;
        float fr = tp - (float)it;
        float a0 = env * (1.0f - fr);
        float a1 = env * fr;

        sData[s][0] = make_float4(ux, uy, uz, a0);
        sData[s][1] = make_float4(a1, __int_as_float(it), Y4, Y5);
        sData[s][2] = make_float4(Y6, Y7, Y8, Y9);
        sData[s][3] = make_float4(Y10, Y11, Y12, Y13);
        sData[s][4] = make_float4(Y14, Y15, 0.f, 0.f);
    }
    __syncthreads();

    float A[16];
#pragma unroll
    for (int k = 0; k < 16; k++) A[k] = 0.f;

    const __half2* tb = g_tblh + (size_t)layer * TBL * 512;
    const float4* vecz = g_veczbuf[p] + b * NN * FF;
    const float s3 = 1.7320508075688772f;

#pragma unroll 4
    for (int s = q * 32; s < q * 32 + 32; s++) {
        float4 d0 = sData[s][0];
        float4 d1 = sData[s][1];
        float a0 = d0.w, a1 = d1.x;
        int it = __float_as_int(d1.y);

        uint4 w = *(const uint4*)(tb + (size_t)it * 512 + (ch << 2));
        float2 f0 = __half22float2(*reinterpret_cast<const __half2*>(&w.x));
        float2 f1 = __half22float2(*reinterpret_cast<const __half2*>(&w.y));
        float2 f2 = __half22float2(*reinterpret_cast<const __half2*>(&w.z));
        float2 f3 = __half22float2(*reinterpret_cast<const __half2*>(&w.w));
        float Rw0 = fmaf(a0, f0.x, a1 * f0.y);
        float Rw1 = fmaf(a0, f1.x, a1 * f1.y);
        float Rw2 = fmaf(a0, f2.x, a1 * f2.y);
        float Rw3 = fmaf(a0, f3.x, a1 * f3.y);

        float4 vz = vecz[s * FF + ch];
        float f = vz.w;
        f = fmaf(vz.x, d0.x, f);
        f = fmaf(vz.y, d0.y, f);
        f = fmaf(vz.z, d0.z, f);

        float t0 = Rw0 * f, t1 = Rw1 * f, t2 = Rw2 * f, t3 = Rw3 * f;
        float t1s = t1 * s3;
        float4 d2 = sData[s][2];
        float4 d3 = sData[s][3];
        float4 d4 = sData[s][4];
        A[0] += t0;
        A[1]  = fmaf(t1s, d0.x, A[1]);
        A[2]  = fmaf(t1s, d0.y, A[2]);
        A[3]  = fmaf(t1s, d0.z, A[3]);
        A[4]  = fmaf(t2, d1.z, A[4]);
        A[5]  = fmaf(t2, d1.w, A[5]);
        A[6]  = fmaf(t2, d2.x, A[6]);
        A[7]  = fmaf(t2, d2.y, A[7]);
        A[8]  = fmaf(t2, d2.z, A[8]);
        A[9]  = fmaf(t3, d2.w, A[9]);
        A[10] = fmaf(t3, d3.x, A[10]);
        A[11] = fmaf(t3, d3.y, A[11]);
        A[12] = fmaf(t3, d3.z, A[12]);
        A[13] = fmaf(t3, d3.w, A[13]);
        A[14] = fmaf(t3, d4.x, A[14]);
        A[15] = fmaf(t3, d4.y, A[15]);
    }

    if (q > 0) {
#pragma unroll
        for (int k = 0; k < 16; k++) red[q - 1][k * 64 + threadIdx.x] = A[k];
    }
    __syncthreads();
    if (q != 0) return;

#pragma unroll
    for (int k = 0; k < 16; k++)
        A[k] = (A[k] + red[0][k * 64 + threadIdx.x] + red[1][k * 64 + threadIdx.x]
                + red[2][k * 64 + threadIdx.x]) * (1.0f / 16.0f);

    float n0 = A[0] * A[0];
    float n1 = A[1] * A[1] + A[2] * A[2] + A[3] * A[3];

    const int co = (layer * 4) * FF + ch;
    float g0 = 1.f + c1w[co]      * n0 + c2w[co]      * n0 * n0 + c3w[co]      * n0 * n0 * n0;
    float g1 = 1.f + c1w[co + FF] * n1 + c2w[co + FF] * n1 * n1 + c3w[co + FF] * n1 * n1 * n1;

    float* dst = g_A4 + ((size_t)(b * NN + r)) * 4 * FF;
    dst[ch]          = A[0] * g0;
    dst[FF + ch]     = A[1] * g1;
    dst[2 * FF + ch] = A[2] * g1;
    dst[3 * FF + ch] = A[3] * g1;
}

// ---------------- node update ----------------------------------------------
// blockDim (32,8): lane owns 4 channels (float4), q = k-slice [q*16, q*16+16)
__global__ __launch_bounds__(256, 4) void k_node(const float* __restrict__ pos_in,
                                                 const float* __restrict__ Wmix0,
                                                 const float* __restrict__ Wmix1,
                                                 const float* __restrict__ Wg1,
                                                 const float* __restrict__ Wg2,
                                                 const float* __restrict__ Wvout,
                                                 const float* __restrict__ Wnode,
                                                 float* __restrict__ out,
                                                 int layer) {
    const int bn = blockIdx.x;
    const int lane = threadIdx.x;
    const int q = threadIdx.y;
    const int tid = q * 32 + lane;
    const int c4 = lane * 4;
    const int p = layer & 1;

    __shared__ float sA[4 * FF];
    __shared__ float part[8][4 * FF];
    __shared__ float sred[4 * FF];
    __shared__ float shp[2][16];
    __shared__ float sh[16];
    __shared__ float rb[3][4];
    __shared__ float zred[FF];

    const float* asrc = g_A4 + (size_t)bn * 4 * FF;
    for (int idx = tid; idx < 4 * FF; idx += 256) sA[idx] = asrc[idx];
    __syncthreads();

    {
        const float* M0 = Wmix0 + layer * FF * FF + c4;
        const float* M1 = Wmix1 + layer * FF * FF + c4;
        float4 sc = make_float4(0.f, 0.f, 0.f, 0.f);
        float4 v0 = sc, v1 = sc, v2 = sc;
#pragma unroll
        for (int kk = 0; kk < 16; kk++) {
            int k = q * 16 + kk;
            float4 m0 = *(const float4*)(M0 + k * FF);
            float4 m1 = *(const float4*)(M1 + k * FF);
            float aS = sA[k], a0 = sA[FF + k], a1 = sA[2 * FF + k], a2 = sA[3 * FF + k];
            sc.x = fmaf(aS, m0.x, sc.x); sc.y = fmaf(aS, m0.y, sc.y);
            sc.z = fmaf(aS, m0.z, sc.z); sc.w = fmaf(aS, m0.w, sc.w);
            v0.x = fmaf(a0, m1.x, v0.x); v0.y = fmaf(a0, m1.y, v0.y);
            v0.z = fmaf(a0, m1.z, v0.z); v0.w = fmaf(a0, m1.w, v0.w);
            v1.x = fmaf(a1, m1.x, v1.x); v1.y = fmaf(a1, m1.y, v1.y);
            v1.z = fmaf(a1, m1.z, v1.z); v1.w = fmaf(a1, m1.w, v1.w);
            v2.x = fmaf(a2, m1.x, v2.x); v2.y = fmaf(a2, m1.y, v2.y);
            v2.z = fmaf(a2, m1.z, v2.z); v2.w = fmaf(a2, m1.w, v2.w);
        }
        *(float4*)&part[q][0 * FF + c4] = sc;
        *(float4*)&part[q][1 * FF + c4] = v0;
        *(float4*)&part[q][2 * FF + c4] = v1;
        *(float4*)&part[q][3 * FF + c4] = v2;
    }
    __syncthreads();

    for (int idx = tid; idx < 4 * FF; idx += 256) {
        float s = 0.f;
#pragma unroll
        for (int qq = 0; qq < 8; qq++) s += part[qq][idx];
        sred[idx] = s;
    }
    __syncthreads();

    if (tid < 32) {
        int cc = tid & 15, hf = tid >> 4;
        const float* G1 = Wg1 + layer * FF * 16 + cc;
        float a = 0.f;
#pragma unroll 8
        for (int kk = 0; kk < 64; kk++) {
            int k = hf * 64 + kk;
            a = fmaf(sred[k], G1[k * 16], a);
        }
        shp[hf][cc] = a;
    }
    __syncthreads();
    if (tid < 16) {
        float a = shp[0][tid] + shp[1][tid];
        sh[tid] = a / (1.0f + expf(-a));
    }
    __syncthreads();

    if (tid < 128) {
        const int c = tid;
        const float* G2 = Wg2 + layer * 16 * FF;
        float gate = 0.f;
#pragma unroll
        for (int j = 0; j < 16; j++) gate = fmaf(sh[j], G2[j * FF + c], gate);
        float w = gate * Wvout[layer * FF + c];
        float m0 = sred[FF + c] * w;
        float m1 = sred[2 * FF + c] * w;
        float m2 = sred[3 * FF + c] * w;
#pragma unroll
        for (int off = 16; off > 0; off >>= 1) {
            m0 += __shfl_down_sync(0xffffffffu, m0, off);
            m1 += __shfl_down_sync(0xffffffffu, m1, off);
            m2 += __shfl_down_sync(0xffffffffu, m2, off);
        }
        if ((c & 31) == 0) {
            int wp = c >> 5;
            rb[0][wp] = m0; rb[1][wp] = m1; rb[2][wp] = m2;
        }
    }
    __syncthreads();
    if (tid < 3) {
        float pnew = g_posbuf[p][bn * 3 + tid] + rb[tid][0] + rb[tid][1] + rb[tid][2] + rb[tid][3];
        g_posbuf[1 - p][bn * 3 + tid] = pnew;
        if (layer == LL - 1)
            out[bn * 3 + tid] = pnew - pos_in[bn * 3 + tid];
    }

    if (layer + 1 < LL) {
        const float* W = Wnode + (layer + 1) * FF * FF + c4;
        float4 acc = make_float4(0.f, 0.f, 0.f, 0.f);
#pragma unroll
        for (int kk = 0; kk < 16; kk++) {
            int k = q * 16 + kk;
            float4 w4 = *(const float4*)(W + k * FF);
            float s = sred[k];
            acc.x = fmaf(s, w4.x, acc.x); acc.y = fmaf(s, w4.y, acc.y);
            acc.z = fmaf(s, w4.z, acc.z); acc.w = fmaf(s, w4.w, acc.w);
        }
        __syncthreads();
        *(float4*)&part[q][c4] = acc;
        __syncthreads();
        if (tid < FF) {
            float s = 0.f;
#pragma unroll
            for (int qq = 0; qq < 8; qq++) s += part[qq][tid];
            zred[tid] = s;
        }
        __syncthreads();
    }

    if (tid < 128) {
        const int c = tid;
        float zn = (layer + 1 < LL) ? zred[c] : 0.f;
        g_veczbuf[1 - p][bn * FF + c] =
            make_float4(sred[FF + c], sred[2 * FF + c], sred[3 * FF + c], zn);
    }
}

// ---------------------------------------------------------------------------
extern "C" void kernel_launch(void* const* d_in, const int* in_sizes, int n_in,
                              void* d_out, int out_size) {
    const float* positions     = (const float*)d_in[0];
    const int*   node_features = (const int*)d_in[1];
    const float* gf            = (const float*)d_in[2];
    const float* W_embed       = (const float*)d_in[3];
    const float* b_embed       = (const float*)d_in[4];
    const float* Wr1           = (const float*)d_in[5];
    const float* br1           = (const float*)d_in[6];
    const float* Wr2           = (const float*)d_in[7];
    const float* Wnode         = (const float*)d_in[8];
    const float* c1w           = (const float*)d_in[9];
    const float* c2w           = (const float*)d_in[10];
    const float* c3w           = (const float*)d_in[11];
    const float* Wmix0         = (const float*)d_in[12];
    const float* Wmix1         = (const float*)d_in[13];
    const float* Wg1           = (const float*)d_in[14];
    const float* Wg2           = (const float*)d_in[15];
    const float* Wvout         = (const float*)d_in[16];
    float* out = (float*)d_out;

    k_prep<<<TBLK * LL + BB * NN, 128>>>(Wr1, br1, Wr2, positions, node_features,
                                         gf, W_embed, b_embed, Wnode);
    for (int i = 0; i < LL; i++) {
        k_msg<<<dim3(NN, BB, 2), dim3(64, 4)>>>(positions, c1w, c2w, c3w, i);
        k_node<<<BB * NN, dim3(32, 8)>>>(positions, Wmix0, Wmix1, Wg1, Wg2, Wvout,
                                         Wnode, out, i);
    }
}

// round 9
// speedup vs baseline: 1.3318x; 1.3318x over previous
#include <cuda_runtime.h>
#include <cuda_fp16.h>
#include <math.h>

#define BB 4
#define NN 128
#define FF 128
#define SS 5
#define TGLOB 32
#define LL 2
#define TBL 512
#define LMAX 16.0f
#define TBL_SCALE (TBL / LMAX)
#define TBLK (TBL / 8)          /* table blocks per layer = 64 */

// ---------------- persistent scratch (device globals; no allocation) ------
__device__ float g_posbuf[2][BB * NN * 3];
__device__ float4 g_veczbuf[2][BB * NN * FF];     // (v0,v1,v2,z) per node-channel
__device__ float g_A4[BB * NN * 4 * FF];          // gated A for k=0..3
__device__ __half2 g_tblh[LL * TBL * 256];        // (w_t,w_{t+1}) pairs, ell 0..1 only
                                                  // layout: [layer][t][c*2 + j]

// ---------------- fused prep: radial tables (ell<=1) + embed/init ---------
__global__ __launch_bounds__(128) void k_prep(const float* __restrict__ Wr1,
                                              const float* __restrict__ br1,
                                              const float* __restrict__ Wr2,
                                              const float* __restrict__ positions,
                                              const int* __restrict__ node_features,
                                              const float* __restrict__ gf,
                                              const float* __restrict__ W_embed,
                                              const float* __restrict__ b_embed,
                                              const float* __restrict__ Wnode) {
    const int c = threadIdx.x;
    if (blockIdx.x < TBLK * LL) {
        const int i = blockIdx.x / TBLK;
        const int tb0 = (blockIdx.x % TBLK) * 8;
        __shared__ float h[9][64];
        if (c < 64) {
            float w1 = Wr1[i * 64 + c];
            float b1 = br1[i * 64 + c];
#pragma unroll
            for (int j = 0; j < 9; j++) {
                float lng = (float)(tb0 + j) * (LMAX / (float)TBL);
                float p = lng * w1 + b1;
                h[j][c] = p / (1.0f + expf(-p));
            }
        }
        __syncthreads();
        const float* W = Wr2 + i * 64 * 512 + c;
        float acc[9][2];
#pragma unroll
        for (int j = 0; j < 9; j++) { acc[j][0] = 0.f; acc[j][1] = 0.f; }
#pragma unroll 4
        for (int m = 0; m < 64; m++) {
            float w0 = W[m * 512 + 0];      // ell 0 weights (cols 0..127)
            float w1v = W[m * 512 + 128];   // ell 1 weights (cols 128..255)
#pragma unroll
            for (int j = 0; j < 9; j++) {
                float hm = h[j][m];
                acc[j][0] = fmaf(hm, w0, acc[j][0]);
                acc[j][1] = fmaf(hm, w1v, acc[j][1]);
            }
        }
#pragma unroll
        for (int j = 0; j < 8; j++) {
            __half2* dst = g_tblh + ((size_t)i * TBL + tb0 + j) * 256 + c * 2;
            dst[0] = __float22half2_rn(make_float2(acc[j][0], acc[j + 1][0]));
            dst[1] = __float22half2_rn(make_float2(acc[j][1], acc[j + 1][1]));
        }
    } else {
        const int bn = blockIdx.x - TBLK * LL;
        const int b = bn / NN;
        int nf = node_features[bn];
        float s = W_embed[(nf - 1) * FF + c] + b_embed[c];
#pragma unroll 8
        for (int t = 0; t < TGLOB; t++)
            s = fmaf(gf[b * TGLOB + t], W_embed[(SS + t) * FF + c], s);
        if (c < 3) g_posbuf[0][bn * 3 + c] = positions[bn * 3 + c];

        __shared__ float srow[FF];
        srow[c] = s;
        __syncthreads();
        float acc = 0.f;
#pragma unroll 8
        for (int k = 0; k < FF; k++)
            acc = fmaf(srow[k], Wnode[k * FF + c], acc);
        g_veczbuf[0][bn * FF + c] = make_float4(0.f, 0.f, 0.f, acc);
    }
}

// ---------------- message gather + gate (ell<=1 only — rest is dead) ------
// blockDim (128,2): c = channel, q = sender half [q*64, q*64+64)
__global__ __launch_bounds__(256, 4) void k_msg(const float* __restrict__ pos_in,
                                                const float* __restrict__ c1w,
                                                const float* __restrict__ c2w,
                                                const float* __restrict__ c3w,
                                                int layer) {
    const int r = blockIdx.x;
    const int b = blockIdx.y;
    const int c = threadIdx.x;
    const int q = threadIdx.y;
    const int tid = q * 128 + c;
    const int p = layer & 1;

    __shared__ float sp[NN * 3];
    __shared__ float sp0[NN * 3];
    __shared__ float4 sData[NN][2];
    __shared__ float red[4 * FF];

    for (int idx = tid; idx < NN * 3; idx += 256) {
        sp[idx]  = g_posbuf[p][b * NN * 3 + idx];
        sp0[idx] = pos_in[b * NN * 3 + idx];
    }
    __syncthreads();

    if (tid < NN) {
        const int s = tid;
        const float rx = sp[r * 3 + 0], ry = sp[r * 3 + 1], rz = sp[r * 3 + 2];
        float dx0 = sp0[r * 3 + 0] - sp0[s * 3 + 0];
        float dy0 = sp0[r * 3 + 1] - sp0[s * 3 + 1];
        float dz0 = sp0[r * 3 + 2] - sp0[s * 3 + 2];
        float l0 = sqrtf(dx0 * dx0 + dy0 * dy0 + dz0 * dz0 + 1e-12f);
        float env = (l0 < 10.0f) ? 0.5f * (cosf(l0 * 0.3141592653589793f) + 1.0f) : 0.0f;
        if (s == r) env = 0.0f;

        float vx = rx - sp[s * 3 + 0];
        float vy = ry - sp[s * 3 + 1];
        float vz = rz - sp[s * 3 + 2];
        float lng = sqrtf(vx * vx + vy * vy + vz * vz + 1e-12f);
        float inv = 1.0f / lng;
        float ux = vx * inv, uy = vy * inv, uz = vz * inv;

        float tp = fminf(lng * TBL_SCALE, (float)TBL - 1.001f);
        int it = (int)tp;
        float fr = tp - (float)it;
        float a0 = env * (1.0f - fr);
        float a1 = env * fr;

        sData[s][0] = make_float4(ux, uy, uz, a0);
        sData[s][1] = make_float4(a1, __int_as_float(it), 0.f, 0.f);
    }
    __syncthreads();

    float A0 = 0.f, A1 = 0.f, A2 = 0.f, A3 = 0.f;

    const __half2* tb = g_tblh + (size_t)layer * TBL * 256;
    const float4* vecz = g_veczbuf[p] + b * NN * FF;
    const float s3 = 1.7320508075688772f;

#pragma unroll 4
    for (int s = q * 64; s < q * 64 + 64; s++) {
        float4 d0 = sData[s][0];
        float4 d1 = sData[s][1];
        float a0 = d0.w, a1 = d1.x;
        int it = __float_as_int(d1.y);

        // one 8B load: 2 half2 pairs = both lerp endpoints for ell 0 and 1
        uint2 w = *(const uint2*)(tb + (size_t)it * 256 + (c << 1));
        float2 f0 = __half22float2(*reinterpret_cast<const __half2*>(&w.x));
        float2 f1 = __half22float2(*reinterpret_cast<const __half2*>(&w.y));
        float Rw0 = fmaf(a0, f0.x, a1 * f0.y);
        float Rw1 = fmaf(a0, f1.x, a1 * f1.y);

        float4 vz = vecz[s * FF + c];
        float f = vz.w;
        f = fmaf(vz.x, d0.x, f);
        f = fmaf(vz.y, d0.y, f);
        f = fmaf(vz.z, d0.z, f);

        float t1s = Rw1 * f * s3;
        A0 = fmaf(Rw0, f, A0);
        A1 = fmaf(t1s, d0.x, A1);
        A2 = fmaf(t1s, d0.y, A2);
        A3 = fmaf(t1s, d0.z, A3);
    }

    if (q == 1) {
        red[c]          = A0;
        red[FF + c]     = A1;
        red[2 * FF + c] = A2;
        red[3 * FF + c] = A3;
    }
    __syncthreads();
    if (q != 0) return;

    A0 = (A0 + red[c])          * (1.0f / 16.0f);
    A1 = (A1 + red[FF + c])     * (1.0f / 16.0f);
    A2 = (A2 + red[2 * FF + c]) * (1.0f / 16.0f);
    A3 = (A3 + red[3 * FF + c]) * (1.0f / 16.0f);

    float n0 = A0 * A0;
    float n1 = A1 * A1 + A2 * A2 + A3 * A3;

    const int co = (layer * 4) * FF + c;
    float g0 = 1.f + c1w[co]      * n0 + c2w[co]      * n0 * n0 + c3w[co]      * n0 * n0 * n0;
    float g1 = 1.f + c1w[co + FF] * n1 + c2w[co + FF] * n1 * n1 + c3w[co + FF] * n1 * n1 * n1;

    float* dst = g_A4 + ((size_t)(b * NN + r)) * 4 * FF;
    dst[c]          = A0 * g0;
    dst[FF + c]     = A1 * g1;
    dst[2 * FF + c] = A2 * g1;
    dst[3 * FF + c] = A3 * g1;
}

// ---------------- node update ----------------------------------------------
// blockDim (32,8): lane owns 4 channels (float4), q = k-slice [q*16, q*16+16)
__global__ __launch_bounds__(256, 4) void k_node(const float* __restrict__ pos_in,
                                                 const float* __restrict__ Wmix0,
                                                 const float* __restrict__ Wmix1,
                                                 const float* __restrict__ Wg1,
                                                 const float* __restrict__ Wg2,
                                                 const float* __restrict__ Wvout,
                                                 const float* __restrict__ Wnode,
                                                 float* __restrict__ out,
                                                 int layer) {
    const int bn = blockIdx.x;
    const int lane = threadIdx.x;
    const int q = threadIdx.y;
    const int tid = q * 32 + lane;
    const int c4 = lane * 4;
    const int p = layer & 1;

    __shared__ float sA[4 * FF];
    __shared__ float part[8][4 * FF];
    __shared__ float sred[4 * FF];
    __shared__ float shp[2][16];
    __shared__ float sh[16];
    __shared__ float rb[3][4];
    __shared__ float zred[FF];

    const float* asrc = g_A4 + (size_t)bn * 4 * FF;
    for (int idx = tid; idx < 4 * FF; idx += 256) sA[idx] = asrc[idx];
    __syncthreads();

    {
        const float* M0 = Wmix0 + layer * FF * FF + c4;
        const float* M1 = Wmix1 + layer * FF * FF + c4;
        float4 sc = make_float4(0.f, 0.f, 0.f, 0.f);
        float4 v0 = sc, v1 = sc, v2 = sc;
#pragma unroll
        for (int kk = 0; kk < 16; kk++) {
            int k = q * 16 + kk;
            float4 m0 = *(const float4*)(M0 + k * FF);
            float4 m1 = *(const float4*)(M1 + k * FF);
            float aS = sA[k], a0 = sA[FF + k], a1 = sA[2 * FF + k], a2 = sA[3 * FF + k];
            sc.x = fmaf(aS, m0.x, sc.x); sc.y = fmaf(aS, m0.y, sc.y);
            sc.z = fmaf(aS, m0.z, sc.z); sc.w = fmaf(aS, m0.w, sc.w);
            v0.x = fmaf(a0, m1.x, v0.x); v0.y = fmaf(a0, m1.y, v0.y);
            v0.z = fmaf(a0, m1.z, v0.z); v0.w = fmaf(a0, m1.w, v0.w);
            v1.x = fmaf(a1, m1.x, v1.x); v1.y = fmaf(a1, m1.y, v1.y);
            v1.z = fmaf(a1, m1.z, v1.z); v1.w = fmaf(a1, m1.w, v1.w);
            v2.x = fmaf(a2, m1.x, v2.x); v2.y = fmaf(a2, m1.y, v2.y);
            v2.z = fmaf(a2, m1.z, v2.z); v2.w = fmaf(a2, m1.w, v2.w);
        }
        *(float4*)&part[q][0 * FF + c4] = sc;
        *(float4*)&part[q][1 * FF + c4] = v0;
        *(float4*)&part[q][2 * FF + c4] = v1;
        *(float4*)&part[q][3 * FF + c4] = v2;
    }
    __syncthreads();

    for (int idx = tid; idx < 4 * FF; idx += 256) {
        float s = 0.f;
#pragma unroll
        for (int qq = 0; qq < 8; qq++) s += part[qq][idx];
        sred[idx] = s;
    }
    __syncthreads();

    if (tid < 32) {
        int cc = tid & 15, hf = tid >> 4;
        const float* G1 = Wg1 + layer * FF * 16 + cc;
        float a = 0.f;
#pragma unroll 8
        for (int kk = 0; kk < 64; kk++) {
            int k = hf * 64 + kk;
            a = fmaf(sred[k], G1[k * 16], a);
        }
        shp[hf][cc] = a;
    }
    __syncthreads();
    if (tid < 16) {
        float a = shp[0][tid] + shp[1][tid];
        sh[tid] = a / (1.0f + expf(-a));
    }
    __syncthreads();

    if (tid < 128) {
        const int c = tid;
        const float* G2 = Wg2 + layer * 16 * FF;
        float gate = 0.f;
#pragma unroll
        for (int j = 0; j < 16; j++) gate = fmaf(sh[j], G2[j * FF + c], gate);
        float w = gate * Wvout[layer * FF + c];
        float m0 = sred[FF + c] * w;
        float m1 = sred[2 * FF + c] * w;
        float m2 = sred[3 * FF + c] * w;
#pragma unroll
        for (int off = 16; off > 0; off >>= 1) {
            m0 += __shfl_down_sync(0xffffffffu, m0, off);
            m1 += __shfl_down_sync(0xffffffffu, m1, off);
            m2 += __shfl_down_sync(0xffffffffu, m2, off);
        }
        if ((c & 31) == 0) {
            int wp = c >> 5;
            rb[0][wp] = m0; rb[1][wp] = m1; rb[2][wp] = m2;
        }
    }
    __syncthreads();
    if (tid < 3) {
        float pnew = g_posbuf[p][bn * 3 + tid] + rb[tid][0] + rb[tid][1] + rb[tid][2] + rb[tid][3];
        g_posbuf[1 - p][bn * 3 + tid] = pnew;
        if (layer == LL - 1)
            out[bn * 3 + tid] = pnew - pos_in[bn * 3 + tid];
    }

    if (layer + 1 < LL) {
        const float* W = Wnode + (layer + 1) * FF * FF + c4;
        float4 acc = make_float4(0.f, 0.f, 0.f, 0.f);
#pragma unroll
        for (int kk = 0; kk < 16; kk++) {
            int k = q * 16 + kk;
            float4 w4 = *(const float4*)(W + k * FF);
            float s = sred[k];
            acc.x = fmaf(s, w4.x, acc.x); acc.y = fmaf(s, w4.y, acc.y);
            acc.z = fmaf(s, w4.z, acc.z); acc.w = fmaf(s, w4.w, acc.w);
        }
        __syncthreads();
        *(float4*)&part[q][c4] = acc;
        __syncthreads();
        if (tid < FF) {
            float s = 0.f;
#pragma unroll
            for (int qq = 0; qq < 8; qq++) s += part[qq][tid];
            zred[tid] = s;
        }
        __syncthreads();
    }

    if (tid < 128) {
        const int c = tid;
        float zn = (layer + 1 < LL) ? zred[c] : 0.f;
        g_veczbuf[1 - p][bn * FF + c] =
            make_float4(sred[FF + c], sred[2 * FF + c], sred[3 * FF + c], zn);
    }
}

// ---------------------------------------------------------------------------
extern "C" void kernel_launch(void* const* d_in, const int* in_sizes, int n_in,
                              void* d_out, int out_size) {
    const float* positions     = (const float*)d_in[0];
    const int*   node_features = (const int*)d_in[1];
    const float* gf            = (const float*)d_in[2];
    const float* W_embed       = (const float*)d_in[3];
    const float* b_embed       = (const float*)d_in[4];
    const float* Wr1           = (const float*)d_in[5];
    const float* br1           = (const float*)d_in[6];
    const float* Wr2           = (const float*)d_in[7];
    const float* Wnode         = (const float*)d_in[8];
    const float* c1w           = (const float*)d_in[9];
    const float* c2w           = (const float*)d_in[10];
    const float* c3w           = (const float*)d_in[11];
    const float* Wmix0         = (const float*)d_in[12];
    const float* Wmix1         = (const float*)d_in[13];
    const float* Wg1           = (const float*)d_in[14];
    const float* Wg2           = (const float*)d_in[15];
    const float* Wvout         = (const float*)d_in[16];
    float* out = (float*)d_out;

    k_prep<<<TBLK * LL + BB * NN, 128>>>(Wr1, br1, Wr2, positions, node_features,
                                         gf, W_embed, b_embed, Wnode);
    for (int i = 0; i < LL; i++) {
        k_msg<<<dim3(NN, BB), dim3(128, 2)>>>(positions, c1w, c2w, c3w, i);
        k_node<<<BB * NN, dim3(32, 8)>>>(positions, Wmix0, Wmix1, Wg1, Wg2, Wvout,
                                         Wnode, out, i);
    }
}

// round 10
// speedup vs baseline: 1.4267x; 1.0713x over previous
#include <cuda_runtime.h>
#include <cuda_fp16.h>
#include <math.h>

#define BB 4
#define NN 128
#define FF 128
#define SS 5
#define TGLOB 32
#define LL 2
#define TBL 512
#define LMAX 16.0f
#define TBL_SCALE (TBL / LMAX)
#define TBLK (TBL / 8)          /* table blocks per layer = 64 */

// ---------------- persistent scratch (device globals; no allocation) ------
__device__ float g_posbuf[2][BB * NN * 3];
__device__ float4 g_veczbuf[2][BB * NN * FF];     // (v0,v1,v2,z) per node-channel
__device__ float g_A4[BB * NN * 4 * FF];          // gated A for k=0..3
__device__ __half2 g_tblh[LL * TBL * 256];        // (w_t,w_{t+1}) pairs, ell 0..1

// ---------------- fused prep: radial tables (ell<=1) + embed/init ---------
__global__ __launch_bounds__(128) void k_prep(const float* __restrict__ Wr1,
                                              const float* __restrict__ br1,
                                              const float* __restrict__ Wr2,
                                              const float* __restrict__ positions,
                                              const int* __restrict__ node_features,
                                              const float* __restrict__ gf,
                                              const float* __restrict__ W_embed,
                                              const float* __restrict__ b_embed,
                                              const float* __restrict__ Wnode) {
    const int c = threadIdx.x;
    if (blockIdx.x < TBLK * LL) {
        const int i = blockIdx.x / TBLK;
        const int tb0 = (blockIdx.x % TBLK) * 8;
        __shared__ float h[9][64];
        if (c < 64) {
            float w1 = Wr1[i * 64 + c];
            float b1 = br1[i * 64 + c];
#pragma unroll
            for (int j = 0; j < 9; j++) {
                float lng = (float)(tb0 + j) * (LMAX / (float)TBL);
                float p = lng * w1 + b1;
                h[j][c] = p / (1.0f + expf(-p));
            }
        }
        __syncthreads();
        const float* W = Wr2 + i * 64 * 512 + c;
        float acc[9][2];
#pragma unroll
        for (int j = 0; j < 9; j++) { acc[j][0] = 0.f; acc[j][1] = 0.f; }
#pragma unroll 4
        for (int m = 0; m < 64; m++) {
            float w0 = W[m * 512 + 0];
            float w1v = W[m * 512 + 128];
#pragma unroll
            for (int j = 0; j < 9; j++) {
                float hm = h[j][m];
                acc[j][0] = fmaf(hm, w0, acc[j][0]);
                acc[j][1] = fmaf(hm, w1v, acc[j][1]);
            }
        }
#pragma unroll
        for (int j = 0; j < 8; j++) {
            __half2* dst = g_tblh + ((size_t)i * TBL + tb0 + j) * 256 + c * 2;
            dst[0] = __float22half2_rn(make_float2(acc[j][0], acc[j + 1][0]));
            dst[1] = __float22half2_rn(make_float2(acc[j][1], acc[j + 1][1]));
        }
    } else {
        const int bn = blockIdx.x - TBLK * LL;
        const int b = bn / NN;
        int nf = node_features[bn];
        float s = W_embed[(nf - 1) * FF + c] + b_embed[c];
#pragma unroll 8
        for (int t = 0; t < TGLOB; t++)
            s = fmaf(gf[b * TGLOB + t], W_embed[(SS + t) * FF + c], s);
        if (c < 3) g_posbuf[0][bn * 3 + c] = positions[bn * 3 + c];

        __shared__ float srow[FF];
        srow[c] = s;
        __syncthreads();
        float acc = 0.f;
#pragma unroll 8
        for (int k = 0; k < FF; k++)
            acc = fmaf(srow[k], Wnode[k * FF + c], acc);
        g_veczbuf[0][bn * FF + c] = make_float4(0.f, 0.f, 0.f, acc);
    }
}

// ---------------- message gather + gate (ell<=1), 2 receivers per block ---
// grid (NN/2, BB); blockDim (128,4): c = channel, q = sender quarter.
__global__ __launch_bounds__(512, 2) void k_msg(const float* __restrict__ pos_in,
                                                const float* __restrict__ c1w,
                                                const float* __restrict__ c2w,
                                                const float* __restrict__ c3w,
                                                int layer) {
    const int r0 = blockIdx.x * 2;
    const int b = blockIdx.y;
    const int c = threadIdx.x;
    const int q = threadIdx.y;
    const int tid = q * 128 + c;
    const int p = layer & 1;

    __shared__ float sp[NN * 3];
    __shared__ float sp0[NN * 3];
    __shared__ float4 sData[2][NN][2];
    __shared__ float red[3][2][4 * FF];

    for (int idx = tid; idx < NN * 3; idx += 512) {
        sp[idx]  = g_posbuf[p][b * NN * 3 + idx];
        sp0[idx] = pos_in[b * NN * 3 + idx];
    }
    __syncthreads();

    // ---- phase 1: per-(receiver, sender) geometry, 256 threads ----
    if (tid < 2 * NN) {
        const int rr = tid >> 7;
        const int s = tid & (NN - 1);
        const int r = r0 + rr;
        const float rx = sp[r * 3 + 0], ry = sp[r * 3 + 1], rz = sp[r * 3 + 2];
        float dx0 = sp0[r * 3 + 0] - sp0[s * 3 + 0];
        float dy0 = sp0[r * 3 + 1] - sp0[s * 3 + 1];
        float dz0 = sp0[r * 3 + 2] - sp0[s * 3 + 2];
        float l0 = sqrtf(dx0 * dx0 + dy0 * dy0 + dz0 * dz0 + 1e-12f);
        float env = (l0 < 10.0f) ? 0.5f * (cosf(l0 * 0.3141592653589793f) + 1.0f) : 0.0f;
        if (s == r) env = 0.0f;

        float vx = rx - sp[s * 3 + 0];
        float vy = ry - sp[s * 3 + 1];
        float vz = rz - sp[s * 3 + 2];
        float lng = sqrtf(vx * vx + vy * vy + vz * vz + 1e-12f);
        float inv = 1.0f / lng;
        float ux = vx * inv, uy = vy * inv, uz = vz * inv;

        float tp = fminf(lng * TBL_SCALE, (float)TBL - 1.001f);
        int it = (int)tp;
        float fr = tp - (float)it;
        float a0 = env * (1.0f - fr);
        float a1 = env * fr;

        sData[rr][s][0] = make_float4(ux, uy, uz, a0);
        sData[rr][s][1] = make_float4(a1, __int_as_float(it), 0.f, 0.f);
    }
    __syncthreads();

    // ---- phase 2: per-channel accumulation; vecz load shared across rr ----
    float A[2][4];
#pragma unroll
    for (int rr = 0; rr < 2; rr++)
#pragma unroll
        for (int k = 0; k < 4; k++) A[rr][k] = 0.f;

    const __half2* tb = g_tblh + (size_t)layer * TBL * 256;
    const float4* vecz = g_veczbuf[p] + b * NN * FF;
    const float s3 = 1.7320508075688772f;

#pragma unroll 4
    for (int s = q * 32; s < q * 32 + 32; s++) {
        float4 vz = vecz[s * FF + c];
#pragma unroll
        for (int rr = 0; rr < 2; rr++) {
            float4 d0 = sData[rr][s][0];
            float4 d1 = sData[rr][s][1];
            float a0 = d0.w, a1 = d1.x;
            int it = __float_as_int(d1.y);

            uint2 w = *(const uint2*)(tb + (size_t)it * 256 + (c << 1));
            float2 f0 = __half22float2(*reinterpret_cast<const __half2*>(&w.x));
            float2 f1 = __half22float2(*reinterpret_cast<const __half2*>(&w.y));
            float Rw0 = fmaf(a0, f0.x, a1 * f0.y);
            float Rw1 = fmaf(a0, f1.x, a1 * f1.y);

            float f = vz.w;
            f = fmaf(vz.x, d0.x, f);
            f = fmaf(vz.y, d0.y, f);
            f = fmaf(vz.z, d0.z, f);

            float t1s = Rw1 * f * s3;
            A[rr][0] = fmaf(Rw0, f, A[rr][0]);
            A[rr][1] = fmaf(t1s, d0.x, A[rr][1]);
            A[rr][2] = fmaf(t1s, d0.y, A[rr][2]);
            A[rr][3] = fmaf(t1s, d0.z, A[rr][3]);
        }
    }

    if (q > 0) {
#pragma unroll
        for (int rr = 0; rr < 2; rr++)
#pragma unroll
            for (int k = 0; k < 4; k++) red[q - 1][rr][k * FF + c] = A[rr][k];
    }
    __syncthreads();
    if (q != 0) return;

#pragma unroll
    for (int rr = 0; rr < 2; rr++) {
        float A0 = (A[rr][0] + red[0][rr][c] + red[1][rr][c] + red[2][rr][c]) * (1.0f / 16.0f);
        float A1 = (A[rr][1] + red[0][rr][FF + c] + red[1][rr][FF + c] + red[2][rr][FF + c]) * (1.0f / 16.0f);
        float A2 = (A[rr][2] + red[0][rr][2 * FF + c] + red[1][rr][2 * FF + c] + red[2][rr][2 * FF + c]) * (1.0f / 16.0f);
        float A3 = (A[rr][3] + red[0][rr][3 * FF + c] + red[1][rr][3 * FF + c] + red[2][rr][3 * FF + c]) * (1.0f / 16.0f);

        float n0 = A0 * A0;
        float n1 = A1 * A1 + A2 * A2 + A3 * A3;

        const int co = (layer * 4) * FF + c;
        float g0 = 1.f + c1w[co]      * n0 + c2w[co]      * n0 * n0 + c3w[co]      * n0 * n0 * n0;
        float g1 = 1.f + c1w[co + FF] * n1 + c2w[co + FF] * n1 * n1 + c3w[co + FF] * n1 * n1 * n1;

        float* dst = g_A4 + ((size_t)(b * NN + r0 + rr)) * 4 * FF;
        dst[c]          = A0 * g0;
        dst[FF + c]     = A1 * g1;
        dst[2 * FF + c] = A2 * g1;
        dst[3 * FF + c] = A3 * g1;
    }
}

// ---------------- node update ----------------------------------------------
// blockDim (32,8): lane owns 4 channels (float4), q = k-slice [q*16, q*16+16)
__global__ __launch_bounds__(256, 4) void k_node(const float* __restrict__ pos_in,
                                                 const float* __restrict__ Wmix0,
                                                 const float* __restrict__ Wmix1,
                                                 const float* __restrict__ Wg1,
                                                 const float* __restrict__ Wg2,
                                                 const float* __restrict__ Wvout,
                                                 const float* __restrict__ Wnode,
                                                 float* __restrict__ out,
                                                 int layer) {
    const int bn = blockIdx.x;
    const int lane = threadIdx.x;
    const int q = threadIdx.y;
    const int tid = q * 32 + lane;
    const int c4 = lane * 4;
    const int p = layer & 1;

    __shared__ float sA[4 * FF];
    __shared__ float part[8][4 * FF];
    __shared__ float sred[4 * FF];
    __shared__ float shp[2][16];
    __shared__ float sh[16];
    __shared__ float rb[3][4];
    __shared__ float zred[FF];

    const float* asrc = g_A4 + (size_t)bn * 4 * FF;
    for (int idx = tid; idx < 4 * FF; idx += 256) sA[idx] = asrc[idx];
    __syncthreads();

    {
        const float* M0 = Wmix0 + layer * FF * FF + c4;
        const float* M1 = Wmix1 + layer * FF * FF + c4;
        float4 sc = make_float4(0.f, 0.f, 0.f, 0.f);
        float4 v0 = sc, v1 = sc, v2 = sc;
#pragma unroll
        for (int kk = 0; kk < 16; kk++) {
            int k = q * 16 + kk;
            float4 m0 = *(const float4*)(M0 + k * FF);
            float4 m1 = *(const float4*)(M1 + k * FF);
            float aS = sA[k], a0 = sA[FF + k], a1 = sA[2 * FF + k], a2 = sA[3 * FF + k];
            sc.x = fmaf(aS, m0.x, sc.x); sc.y = fmaf(aS, m0.y, sc.y);
            sc.z = fmaf(aS, m0.z, sc.z); sc.w = fmaf(aS, m0.w, sc.w);
            v0.x = fmaf(a0, m1.x, v0.x); v0.y = fmaf(a0, m1.y, v0.y);
            v0.z = fmaf(a0, m1.z, v0.z); v0.w = fmaf(a0, m1.w, v0.w);
            v1.x = fmaf(a1, m1.x, v1.x); v1.y = fmaf(a1, m1.y, v1.y);
            v1.z = fmaf(a1, m1.z, v1.z); v1.w = fmaf(a1, m1.w, v1.w);
            v2.x = fmaf(a2, m1.x, v2.x); v2.y = fmaf(a2, m1.y, v2.y);
            v2.z = fmaf(a2, m1.z, v2.z); v2.w = fmaf(a2, m1.w, v2.w);
        }
        *(float4*)&part[q][0 * FF + c4] = sc;
        *(float4*)&part[q][1 * FF + c4] = v0;
        *(float4*)&part[q][2 * FF + c4] = v1;
        *(float4*)&part[q][3 * FF + c4] = v2;
    }
    __syncthreads();

    for (int idx = tid; idx < 4 * FF; idx += 256) {
        float s = 0.f;
#pragma unroll
        for (int qq = 0; qq < 8; qq++) s += part[qq][idx];
        sred[idx] = s;
    }
    __syncthreads();

    if (tid < 32) {
        int cc = tid & 15, hf = tid >> 4;
        const float* G1 = Wg1 + layer * FF * 16 + cc;
        float a = 0.f;
#pragma unroll 8
        for (int kk = 0; kk < 64; kk++) {
            int k = hf * 64 + kk;
            a = fmaf(sred[k], G1[k * 16], a);
        }
        shp[hf][cc] = a;
    }
    __syncthreads();
    if (tid < 16) {
        float a = shp[0][tid] + shp[1][tid];
        sh[tid] = a / (1.0f + expf(-a));
    }
    __syncthreads();

    if (tid < 128) {
        const int c = tid;
        const float* G2 = Wg2 + layer * 16 * FF;
        float gate = 0.f;
#pragma unroll
        for (int j = 0; j < 16; j++) gate = fmaf(sh[j], G2[j * FF + c], gate);
        float w = gate * Wvout[layer * FF + c];
        float m0 = sred[FF + c] * w;
        float m1 = sred[2 * FF + c] * w;
        float m2 = sred[3 * FF + c] * w;
#pragma unroll
        for (int off = 16; off > 0; off >>= 1) {
            m0 += __shfl_down_sync(0xffffffffu, m0, off);
            m1 += __shfl_down_sync(0xffffffffu, m1, off);
            m2 += __shfl_down_sync(0xffffffffu, m2, off);
        }
        if ((c & 31) == 0) {
            int wp = c >> 5;
            rb[0][wp] = m0; rb[1][wp] = m1; rb[2][wp] = m2;
        }
    }
    __syncthreads();
    if (tid < 3) {
        float pnew = g_posbuf[p][bn * 3 + tid] + rb[tid][0] + rb[tid][1] + rb[tid][2] + rb[tid][3];
        g_posbuf[1 - p][bn * 3 + tid] = pnew;
        if (layer == LL - 1)
            out[bn * 3 + tid] = pnew - pos_in[bn * 3 + tid];
    }

    if (layer + 1 < LL) {
        const float* W = Wnode + (layer + 1) * FF * FF + c4;
        float4 acc = make_float4(0.f, 0.f, 0.f, 0.f);
#pragma unroll
        for (int kk = 0; kk < 16; kk++) {
            int k = q * 16 + kk;
            float4 w4 = *(const float4*)(W + k * FF);
            float s = sred[k];
            acc.x = fmaf(s, w4.x, acc.x); acc.y = fmaf(s, w4.y, acc.y);
            acc.z = fmaf(s, w4.z, acc.z); acc.w = fmaf(s, w4.w, acc.w);
        }
        __syncthreads();
        *(float4*)&part[q][c4] = acc;
        __syncthreads();
        if (tid < FF) {
            float s = 0.f;
#pragma unroll
            for (int qq = 0; qq < 8; qq++) s += part[qq][tid];
            zred[tid] = s;
        }
        __syncthreads();
    }

    if (tid < 128) {
        const int c = tid;
        float zn = (layer + 1 < LL) ? zred[c] : 0.f;
        g_veczbuf[1 - p][bn * FF + c] =
            make_float4(sred[FF + c], sred[2 * FF + c], sred[3 * FF + c], zn);
    }
}

// ---------------------------------------------------------------------------
extern "C" void kernel_launch(void* const* d_in, const int* in_sizes, int n_in,
                              void* d_out, int out_size) {
    const float* positions     = (const float*)d_in[0];
    const int*   node_features = (const int*)d_in[1];
    const float* gf            = (const float*)d_in[2];
    const float* W_embed       = (const float*)d_in[3];
    const float* b_embed       = (const float*)d_in[4];
    const float* Wr1           = (const float*)d_in[5];
    const float* br1           = (const float*)d_in[6];
    const float* Wr2           = (const float*)d_in[7];
    const float* Wnode         = (const float*)d_in[8];
    const float* c1w           = (const float*)d_in[9];
    const float* c2w           = (const float*)d_in[10];
    const float* c3w           = (const float*)d_in[11];
    const float* Wmix0         = (const float*)d_in[12];
    const float* Wmix1         = (const float*)d_in[13];
    const float* Wg1           = (const float*)d_in[14];
    const float* Wg2           = (const float*)d_in[15];
    const float* Wvout         = (const float*)d_in[16];
    float* out = (float*)d_out;

    k_prep<<<TBLK * LL + BB * NN, 128>>>(Wr1, br1, Wr2, positions, node_features,
                                         gf, W_embed, b_embed, Wnode);
    for (int i = 0; i < LL; i++) {
        k_msg<<<dim3(NN / 2, BB), dim3(128, 4)>>>(positions, c1w, c2w, c3w, i);
        k_node<<<BB * NN, dim3(32, 8)>>>(positions, Wmix0, Wmix1, Wg1, Wg2, Wvout,
                                         Wnode, out, i);
    }
}

// round 11
// speedup vs baseline: 1.4685x; 1.0292x over previous
#include <cuda_runtime.h>
#include <cuda_fp16.h>
#include <math.h>

#define BB 4
#define NN 128
#define FF 128
#define SS 5
#define TGLOB 32
#define LL 2
#define TBL 512
#define LMAX 16.0f
#define TBL_SCALE (TBL / LMAX)
#define TBLK (TBL / 8)          /* table blocks per layer = 64 */

// ---------------- persistent scratch (device globals; no allocation) ------
__device__ float g_posbuf[2][BB * NN * 3];
__device__ uint2 g_veczbuf[2][BB * NN * FF];      // half2(v0,v1), half2(v2,z)
__device__ float g_A4[BB * NN * 4 * FF];          // gated A for k=0..3
__device__ __half2 g_tblh[LL * TBL * 256];        // (w_t,w_{t+1}) pairs, ell 0..1
                                                  // ell0 pre-scaled by 1/16,
                                                  // ell1 by sqrt(3)/16

__device__ __forceinline__ unsigned pack2(float a, float b) {
    __half2 h = __floats2half2_rn(a, b);
    return *reinterpret_cast<unsigned*>(&h);
}
__device__ __forceinline__ float2 unpack2(unsigned u) {
    __half2 h = *reinterpret_cast<__half2*>(&u);
    return __half22float2(h);
}

// ---------------- fused prep: radial tables (ell<=1) + embed/init ---------
__global__ __launch_bounds__(128) void k_prep(const float* __restrict__ Wr1,
                                              const float* __restrict__ br1,
                                              const float* __restrict__ Wr2,
                                              const float* __restrict__ positions,
                                              const int* __restrict__ node_features,
                                              const float* __restrict__ gf,
                                              const float* __restrict__ W_embed,
                                              const float* __restrict__ b_embed,
                                              const float* __restrict__ Wnode) {
    const int c = threadIdx.x;
    if (blockIdx.x < TBLK * LL) {
        const int i = blockIdx.x / TBLK;
        const int tb0 = (blockIdx.x % TBLK) * 8;
        __shared__ float h[9][64];
        if (c < 64) {
            float w1 = Wr1[i * 64 + c];
            float b1 = br1[i * 64 + c];
#pragma unroll
            for (int j = 0; j < 9; j++) {
                float lng = (float)(tb0 + j) * (LMAX / (float)TBL);
                float p = lng * w1 + b1;
                h[j][c] = p / (1.0f + expf(-p));
            }
        }
        __syncthreads();
        const float* W = Wr2 + i * 64 * 512 + c;
        float acc[9][2];
#pragma unroll
        for (int j = 0; j < 9; j++) { acc[j][0] = 0.f; acc[j][1] = 0.f; }
#pragma unroll 4
        for (int m = 0; m < 64; m++) {
            float w0 = W[m * 512 + 0];
            float w1v = W[m * 512 + 128];
#pragma unroll
            for (int j = 0; j < 9; j++) {
                float hm = h[j][m];
                acc[j][0] = fmaf(hm, w0, acc[j][0]);
                acc[j][1] = fmaf(hm, w1v, acc[j][1]);
            }
        }
        const float sc0 = 1.0f / 16.0f;
        const float sc1 = 1.7320508075688772f / 16.0f;
#pragma unroll
        for (int j = 0; j < 8; j++) {
            __half2* dst = g_tblh + ((size_t)i * TBL + tb0 + j) * 256 + c * 2;
            dst[0] = __float22half2_rn(make_float2(acc[j][0] * sc0, acc[j + 1][0] * sc0));
            dst[1] = __float22half2_rn(make_float2(acc[j][1] * sc1, acc[j + 1][1] * sc1));
        }
    } else {
        const int bn = blockIdx.x - TBLK * LL;
        const int b = bn / NN;
        int nf = node_features[bn];
        float s = W_embed[(nf - 1) * FF + c] + b_embed[c];
#pragma unroll 8
        for (int t = 0; t < TGLOB; t++)
            s = fmaf(gf[b * TGLOB + t], W_embed[(SS + t) * FF + c], s);
        if (c < 3) g_posbuf[0][bn * 3 + c] = positions[bn * 3 + c];

        __shared__ float srow[FF];
        srow[c] = s;
        __syncthreads();
        float acc = 0.f;
#pragma unroll 8
        for (int k = 0; k < FF; k++)
            acc = fmaf(srow[k], Wnode[k * FF + c], acc);
        g_veczbuf[0][bn * FF + c] = make_uint2(pack2(0.f, 0.f), pack2(0.f, acc));
    }
}

// ---------------- message gather + gate (ell<=1), 2 receivers per block ---
// grid (NN/2, BB); blockDim (128,4): c = channel, q = sender quarter.
__global__ __launch_bounds__(512, 2) void k_msg(const float* __restrict__ pos_in,
                                                const float* __restrict__ c1w,
                                                const float* __restrict__ c2w,
                                                const float* __restrict__ c3w,
                                                int layer) {
    const int r0 = blockIdx.x * 2;
    const int b = blockIdx.y;
    const int c = threadIdx.x;
    const int q = threadIdx.y;
    const int tid = q * 128 + c;
    const int p = layer & 1;

    __shared__ float sp[NN * 3];
    __shared__ float sp0[NN * 3];
    __shared__ float4 sData[2][NN];
    __shared__ float2 sD2[2][NN];
    __shared__ float red[3][2][4 * FF];

    for (int idx = tid; idx < NN * 3; idx += 512) {
        sp[idx]  = g_posbuf[p][b * NN * 3 + idx];
        sp0[idx] = pos_in[b * NN * 3 + idx];
    }
    __syncthreads();

    // ---- phase 1: per-(receiver, sender) geometry, 256 threads ----
    if (tid < 2 * NN) {
        const int rr = tid >> 7;
        const int s = tid & (NN - 1);
        const int r = r0 + rr;
        const float rx = sp[r * 3 + 0], ry = sp[r * 3 + 1], rz = sp[r * 3 + 2];
        float dx0 = sp0[r * 3 + 0] - sp0[s * 3 + 0];
        float dy0 = sp0[r * 3 + 1] - sp0[s * 3 + 1];
        float dz0 = sp0[r * 3 + 2] - sp0[s * 3 + 2];
        float l0 = sqrtf(dx0 * dx0 + dy0 * dy0 + dz0 * dz0 + 1e-12f);
        float env = (l0 < 10.0f) ? 0.5f * (cosf(l0 * 0.3141592653589793f) + 1.0f) : 0.0f;
        if (s == r) env = 0.0f;

        float vx = rx - sp[s * 3 + 0];
        float vy = ry - sp[s * 3 + 1];
        float vz = rz - sp[s * 3 + 2];
        float lng = sqrtf(vx * vx + vy * vy + vz * vz + 1e-12f);
        float inv = 1.0f / lng;
        float ux = vx * inv, uy = vy * inv, uz = vz * inv;

        float tp = fminf(lng * TBL_SCALE, (float)TBL - 1.001f);
        int it = (int)tp;
        float fr = tp - (float)it;
        float a0 = env * (1.0f - fr);
        float a1 = env * fr;

        sData[rr][s] = make_float4(ux, uy, uz, a0);
        sD2[rr][s]   = make_float2(a1, __int_as_float(it));
    }
    __syncthreads();

    // ---- phase 2: per-channel accumulation; vecz load shared across rr ----
    float A[2][4];
#pragma unroll
    for (int rr = 0; rr < 2; rr++)
#pragma unroll
        for (int k = 0; k < 4; k++) A[rr][k] = 0.f;

    const __half2* tb = g_tblh + (size_t)layer * TBL * 256;
    const uint2* vecz = g_veczbuf[p] + b * NN * FF;

#pragma unroll 4
    for (int s = q * 32; s < q * 32 + 32; s++) {
        uint2 vzp = vecz[s * FF + c];
        float2 v01 = unpack2(vzp.x);
        float2 v2z = unpack2(vzp.y);
#pragma unroll
        for (int rr = 0; rr < 2; rr++) {
            float4 d0 = sData[rr][s];
            float2 d1 = sD2[rr][s];
            float a0 = d0.w, a1 = d1.x;
            int it = __float_as_int(d1.y);

            uint2 w = *(const uint2*)(tb + (size_t)it * 256 + (c << 1));
            float2 f0 = unpack2(w.x);
            float2 f1 = unpack2(w.y);
            float Rw0 = fmaf(a0, f0.x, a1 * f0.y);
            float Rw1 = fmaf(a0, f1.x, a1 * f1.y);

            float f = v2z.y;
            f = fmaf(v01.x, d0.x, f);
            f = fmaf(v01.y, d0.y, f);
            f = fmaf(v2z.x, d0.z, f);

            float t1 = Rw1 * f;
            A[rr][0] = fmaf(Rw0, f, A[rr][0]);
            A[rr][1] = fmaf(t1, d0.x, A[rr][1]);
            A[rr][2] = fmaf(t1, d0.y, A[rr][2]);
            A[rr][3] = fmaf(t1, d0.z, A[rr][3]);
        }
    }

    if (q > 0) {
#pragma unroll
        for (int rr = 0; rr < 2; rr++)
#pragma unroll
            for (int k = 0; k < 4; k++) red[q - 1][rr][k * FF + c] = A[rr][k];
    }
    __syncthreads();
    if (q != 0) return;

#pragma unroll
    for (int rr = 0; rr < 2; rr++) {
        float A0 = A[rr][0] + red[0][rr][c] + red[1][rr][c] + red[2][rr][c];
        float A1 = A[rr][1] + red[0][rr][FF + c] + red[1][rr][FF + c] + red[2][rr][FF + c];
        float A2 = A[rr][2] + red[0][rr][2 * FF + c] + red[1][rr][2 * FF + c] + red[2][rr][2 * FF + c];
        float A3 = A[rr][3] + red[0][rr][3 * FF + c] + red[1][rr][3 * FF + c] + red[2][rr][3 * FF + c];

        float n0 = A0 * A0;
        float n1 = A1 * A1 + A2 * A2 + A3 * A3;

        const int co = (layer * 4) * FF + c;
        float g0 = 1.f + c1w[co]      * n0 + c2w[co]      * n0 * n0 + c3w[co]      * n0 * n0 * n0;
        float g1 = 1.f + c1w[co + FF] * n1 + c2w[co + FF] * n1 * n1 + c3w[co + FF] * n1 * n1 * n1;

        float* dst = g_A4 + ((size_t)(b * NN + r0 + rr)) * 4 * FF;
        dst[c]          = A0 * g0;
        dst[FF + c]     = A1 * g1;
        dst[2 * FF + c] = A2 * g1;
        dst[3 * FF + c] = A3 * g1;
    }
}

// ---------------- node update: 2 nodes per block ---------------------------
// blockDim (32,8): lane owns 4 channels (float4), q = k-slice [q*16, q*16+16)
__global__ __launch_bounds__(256, 4) void k_node(const float* __restrict__ pos_in,
                                                 const float* __restrict__ Wmix0,
                                                 const float* __restrict__ Wmix1,
                                                 const float* __restrict__ Wg1,
                                                 const float* __restrict__ Wg2,
                                                 const float* __restrict__ Wvout,
                                                 const float* __restrict__ Wnode,
                                                 float* __restrict__ out,
                                                 int layer) {
    const int bn0 = blockIdx.x * 2;
    const int lane = threadIdx.x;
    const int q = threadIdx.y;
    const int tid = q * 32 + lane;
    const int c4 = lane * 4;
    const int p = layer & 1;

    __shared__ float sA[2 * 4 * FF];       // [n][row][c]
    __shared__ float part[8][2 * 4 * FF];  // 32 KB
    __shared__ float sred[2 * 4 * FF];
    __shared__ float shp[2][2][16];
    __shared__ float sh[2][16];
    __shared__ float rb[2][3][4];
    __shared__ float zred[2][FF];

    const float* asrc = g_A4 + (size_t)bn0 * 4 * FF;
    for (int idx = tid; idx < 2 * 4 * FF; idx += 256) sA[idx] = asrc[idx];
    __syncthreads();

    // ---- Wmix0/Wmix1 GEMV for both nodes, weights loaded once ----
    {
        const float* M0 = Wmix0 + layer * FF * FF + c4;
        const float* M1 = Wmix1 + layer * FF * FF + c4;
        float4 acc[2][4];
#pragma unroll
        for (int n = 0; n < 2; n++)
#pragma unroll
            for (int d = 0; d < 4; d++) acc[n][d] = make_float4(0.f, 0.f, 0.f, 0.f);
#pragma unroll
        for (int kk = 0; kk < 16; kk++) {
            int k = q * 16 + kk;
            float4 m0 = *(const float4*)(M0 + k * FF);
            float4 m1 = *(const float4*)(M1 + k * FF);
#pragma unroll
            for (int n = 0; n < 2; n++) {
                const float* an = sA + n * 512;
                float aS = an[k], a0 = an[FF + k], a1 = an[2 * FF + k], a2 = an[3 * FF + k];
                acc[n][0].x = fmaf(aS, m0.x, acc[n][0].x); acc[n][0].y = fmaf(aS, m0.y, acc[n][0].y);
                acc[n][0].z = fmaf(aS, m0.z, acc[n][0].z); acc[n][0].w = fmaf(aS, m0.w, acc[n][0].w);
                acc[n][1].x = fmaf(a0, m1.x, acc[n][1].x); acc[n][1].y = fmaf(a0, m1.y, acc[n][1].y);
                acc[n][1].z = fmaf(a0, m1.z, acc[n][1].z); acc[n][1].w = fmaf(a0, m1.w, acc[n][1].w);
                acc[n][2].x = fmaf(a1, m1.x, acc[n][2].x); acc[n][2].y = fmaf(a1, m1.y, acc[n][2].y);
                acc[n][2].z = fmaf(a1, m1.z, acc[n][2].z); acc[n][2].w = fmaf(a1, m1.w, acc[n][2].w);
                acc[n][3].x = fmaf(a2, m1.x, acc[n][3].x); acc[n][3].y = fmaf(a2, m1.y, acc[n][3].y);
                acc[n][3].z = fmaf(a2, m1.z, acc[n][3].z); acc[n][3].w = fmaf(a2, m1.w, acc[n][3].w);
            }
        }
#pragma unroll
        for (int n = 0; n < 2; n++)
#pragma unroll
            for (int d = 0; d < 4; d++)
                *(float4*)&part[q][n * 512 + d * FF + c4] = acc[n][d];
    }
    __syncthreads();

    for (int idx = tid; idx < 2 * 4 * FF; idx += 256) {
        float s = 0.f;
#pragma unroll
        for (int qq = 0; qq < 8; qq++) s += part[qq][idx];
        sred[idx] = s;
    }
    __syncthreads();

    // ---- Wg1 (128->16) for both nodes: 64 threads ----
    if (tid < 64) {
        int n = tid >> 5, sub = tid & 31;
        int cc = sub & 15, hf = sub >> 4;
        const float* G1 = Wg1 + layer * FF * 16 + cc;
        const float* sn = sred + n * 512;
        float a = 0.f;
#pragma unroll 8
        for (int kk = 0; kk < 64; kk++) {
            int k = hf * 64 + kk;
            a = fmaf(sn[k], G1[k * 16], a);
        }
        shp[n][hf][cc] = a;
    }
    __syncthreads();
    if (tid < 32) {
        int n = tid >> 4, cc = tid & 15;
        float a = shp[n][0][cc] + shp[n][1][cc];
        sh[n][cc] = a / (1.0f + expf(-a));
    }
    __syncthreads();

    // ---- gate + position reduce: all 256 threads (n = tid>>7) ----
    {
        const int n = tid >> 7;
        const int c = tid & 127;
        const float* G2 = Wg2 + layer * 16 * FF;
        float gate = 0.f;
#pragma unroll
        for (int j = 0; j < 16; j++) gate = fmaf(sh[n][j], G2[j * FF + c], gate);
        float w = gate * Wvout[layer * FF + c];
        const float* sn = sred + n * 512;
        float m0 = sn[FF + c] * w;
        float m1 = sn[2 * FF + c] * w;
        float m2 = sn[3 * FF + c] * w;
#pragma unroll
        for (int off = 16; off > 0; off >>= 1) {
            m0 += __shfl_down_sync(0xffffffffu, m0, off);
            m1 += __shfl_down_sync(0xffffffffu, m1, off);
            m2 += __shfl_down_sync(0xffffffffu, m2, off);
        }
        if ((c & 31) == 0) {
            int wp = (tid >> 5) & 3;
            rb[n][0][wp] = m0; rb[n][1][wp] = m1; rb[n][2][wp] = m2;
        }
    }
    __syncthreads();
    if (tid < 6) {
        int n = tid / 3, d = tid - n * 3;
        int bn = bn0 + n;
        float pnew = g_posbuf[p][bn * 3 + d]
                   + rb[n][d][0] + rb[n][d][1] + rb[n][d][2] + rb[n][d][3];
        g_posbuf[1 - p][bn * 3 + d] = pnew;
        if (layer == LL - 1)
            out[bn * 3 + d] = pnew - pos_in[bn * 3 + d];
    }

    // ---- next-layer z GEMV for both nodes, weights loaded once ----
    if (layer + 1 < LL) {
        const float* W = Wnode + (layer + 1) * FF * FF + c4;
        float4 zacc[2];
        zacc[0] = make_float4(0.f, 0.f, 0.f, 0.f);
        zacc[1] = zacc[0];
#pragma unroll
        for (int kk = 0; kk < 16; kk++) {
            int k = q * 16 + kk;
            float4 w4 = *(const float4*)(W + k * FF);
            float s0 = sred[k], s1 = sred[512 + k];
            zacc[0].x = fmaf(s0, w4.x, zacc[0].x); zacc[0].y = fmaf(s0, w4.y, zacc[0].y);
            zacc[0].z = fmaf(s0, w4.z, zacc[0].z); zacc[0].w = fmaf(s0, w4.w, zacc[0].w);
            zacc[1].x = fmaf(s1, w4.x, zacc[1].x); zacc[1].y = fmaf(s1, w4.y, zacc[1].y);
            zacc[1].z = fmaf(s1, w4.z, zacc[1].z); zacc[1].w = fmaf(s1, w4.w, zacc[1].w);
        }
        *(float4*)&part[q][c4]      = zacc[0];
        *(float4*)&part[q][FF + c4] = zacc[1];
        __syncthreads();
        {
            const int n = tid >> 7;
            const int c = tid & 127;
            float s = 0.f;
#pragma unroll
            for (int qq = 0; qq < 8; qq++) s += part[qq][n * FF + c];
            zred[n][c] = s;
        }
        __syncthreads();
    }

    {
        const int n = tid >> 7;
        const int c = tid & 127;
        const float* sn = sred + n * 512;
        float zn = (layer + 1 < LL) ? zred[n][c] : 0.f;
        g_veczbuf[1 - p][(bn0 + n) * FF + c] =
            make_uint2(pack2(sn[FF + c], sn[2 * FF + c]), pack2(sn[3 * FF + c], zn));
    }
}

// ---------------------------------------------------------------------------
extern "C" void kernel_launch(void* const* d_in, const int* in_sizes, int n_in,
                              void* d_out, int out_size) {
    const float* positions     = (const float*)d_in[0];
    const int*   node_features = (const int*)d_in[1];
    const float* gf            = (const float*)d_in[2];
    const float* W_embed       = (const float*)d_in[3];
    const float* b_embed       = (const float*)d_in[4];
    const float* Wr1           = (const float*)d_in[5];
    const float* br1           = (const float*)d_in[6];
    const float* Wr2           = (const float*)d_in[7];
    const float* Wnode         = (const float*)d_in[8];
    const float* c1w           = (const float*)d_in[9];
    const float* c2w           = (const float*)d_in[10];
    const float* c3w           = (const float*)d_in[11];
    const float* Wmix0         = (const float*)d_in[12];
    const float* Wmix1         = (const float*)d_in[13];
    const float* Wg1           = (const float*)d_in[14];
    const float* Wg2           = (const float*)d_in[15];
    const float* Wvout         = (const float*)d_in[16];
    float* out = (float*)d_out;

    k_prep<<<TBLK * LL + BB * NN, 128>>>(Wr1, br1, Wr2, positions, node_features,
                                         gf, W_embed, b_embed, Wnode);
    for (int i = 0; i < LL; i++) {
        k_msg<<<dim3(NN / 2, BB), dim3(128, 4)>>>(positions, c1w, c2w, c3w, i);
        k_node<<<BB * NN / 2, dim3(32, 8)>>>(positions, Wmix0, Wmix1, Wg1, Wg2, Wvout,
                                             Wnode, out, i);
    }
}

// round 12
// speedup vs baseline: 1.5409x; 1.0493x over previous
#include <cuda_runtime.h>
#include <cuda_fp16.h>
#include <math.h>

#define BB 4
#define NN 128
#define FF 128
#define SS 5
#define TGLOB 32
#define LL 2
#define TBL 512
#define LMAX 16.0f
#define TBL_SCALE (TBL / LMAX)
#define TBLK (TBL / 8)          /* table blocks per layer = 64 */

// ---------------- persistent scratch (device globals; no allocation) ------
__device__ float g_posbuf[2][BB * NN * 3];
__device__ uint2 g_veczbuf[2][BB * NN * FF];      // half2(v0,v1), half2(v2,z)
__device__ __half2 g_tblh[LL * TBL * 256];        // (w_t,w_{t+1}) pairs, ell 0..1
                                                  // ell0 pre-scaled by 1/16,
                                                  // ell1 by sqrt(3)/16

__device__ __forceinline__ unsigned pack2(float a, float b) {
    __half2 h = __floats2half2_rn(a, b);
    return *reinterpret_cast<unsigned*>(&h);
}
__device__ __forceinline__ float2 unpack2(unsigned u) {
    __half2 h = *reinterpret_cast<__half2*>(&u);
    return __half22float2(h);
}

// ---------------- fused prep: radial tables (ell<=1) + embed/init ---------
__global__ __launch_bounds__(128) void k_prep(const float* __restrict__ Wr1,
                                              const float* __restrict__ br1,
                                              const float* __restrict__ Wr2,
                                              const float* __restrict__ positions,
                                              const int* __restrict__ node_features,
                                              const float* __restrict__ gf,
                                              const float* __restrict__ W_embed,
                                              const float* __restrict__ b_embed,
                                              const float* __restrict__ Wnode) {
    const int c = threadIdx.x;
    if (blockIdx.x < TBLK * LL) {
        const int i = blockIdx.x / TBLK;
        const int tb0 = (blockIdx.x % TBLK) * 8;
        __shared__ float h[9][64];
        if (c < 64) {
            float w1 = Wr1[i * 64 + c];
            float b1 = br1[i * 64 + c];
#pragma unroll
            for (int j = 0; j < 9; j++) {
                float lng = (float)(tb0 + j) * (LMAX / (float)TBL);
                float p = lng * w1 + b1;
                h[j][c] = p / (1.0f + expf(-p));
            }
        }
        __syncthreads();
        const float* W = Wr2 + i * 64 * 512 + c;
        float acc[9][2];
#pragma unroll
        for (int j = 0; j < 9; j++) { acc[j][0] = 0.f; acc[j][1] = 0.f; }
#pragma unroll 4
        for (int m = 0; m < 64; m++) {
            float w0 = W[m * 512 + 0];
            float w1v = W[m * 512 + 128];
#pragma unroll
            for (int j = 0; j < 9; j++) {
                float hm = h[j][m];
                acc[j][0] = fmaf(hm, w0, acc[j][0]);
                acc[j][1] = fmaf(hm, w1v, acc[j][1]);
            }
        }
        const float sc0 = 1.0f / 16.0f;
        const float sc1 = 1.7320508075688772f / 16.0f;
#pragma unroll
        for (int j = 0; j < 8; j++) {
            __half2* dst = g_tblh + ((size_t)i * TBL + tb0 + j) * 256 + c * 2;
            dst[0] = __float22half2_rn(make_float2(acc[j][0] * sc0, acc[j + 1][0] * sc0));
            dst[1] = __float22half2_rn(make_float2(acc[j][1] * sc1, acc[j + 1][1] * sc1));
        }
    } else {
        const int bn = blockIdx.x - TBLK * LL;
        const int b = bn / NN;
        int nf = node_features[bn];
        float s = W_embed[(nf - 1) * FF + c] + b_embed[c];
#pragma unroll 8
        for (int t = 0; t < TGLOB; t++)
            s = fmaf(gf[b * TGLOB + t], W_embed[(SS + t) * FF + c], s);
        if (c < 3) g_posbuf[0][bn * 3 + c] = positions[bn * 3 + c];

        __shared__ float srow[FF];
        srow[c] = s;
        __syncthreads();
        float acc = 0.f;
#pragma unroll 8
        for (int k = 0; k < FF; k++)
            acc = fmaf(srow[k], Wnode[k * FF + c], acc);
        g_veczbuf[0][bn * FF + c] = make_uint2(pack2(0.f, 0.f), pack2(0.f, acc));
    }
}

// ---------------- fused layer: msg (2 receivers) + node update ------------
// grid (NN/2, BB); blockDim (128,4). A4 passes through smem only.
__global__ __launch_bounds__(512, 2) void k_layer(const float* __restrict__ pos_in,
                                                  const float* __restrict__ c1w,
                                                  const float* __restrict__ c2w,
                                                  const float* __restrict__ c3w,
                                                  const float* __restrict__ Wmix0,
                                                  const float* __restrict__ Wmix1,
                                                  const float* __restrict__ Wg1,
                                                  const float* __restrict__ Wg2,
                                                  const float* __restrict__ Wvout,
                                                  const float* __restrict__ Wnode,
                                                  float* __restrict__ out,
                                                  int layer) {
    const int r0 = blockIdx.x * 2;
    const int b = blockIdx.y;
    const int c = threadIdx.x;
    const int q = threadIdx.y;
    const int tid = q * 128 + c;
    const int p = layer & 1;

    __shared__ float sp[NN * 3];
    __shared__ float sp0[NN * 3];
    __shared__ float4 sData[2][NN];
    __shared__ float2 sD2[2][NN];
    __shared__ float rp[8 * 1024];   // msg: red[3][2][512]; node: part[8][2*512]
    __shared__ float sA[2 * 512];
    __shared__ float sred[2 * 512];
    __shared__ float shp[2][2][16];
    __shared__ float sh[2][16];
    __shared__ float rb[2][3][4];
    __shared__ float zred[2][FF];

    for (int idx = tid; idx < NN * 3; idx += 512) {
        sp[idx]  = g_posbuf[p][b * NN * 3 + idx];
        sp0[idx] = pos_in[b * NN * 3 + idx];
    }
    __syncthreads();

    // ---- phase 1: per-(receiver, sender) geometry, 256 threads ----
    if (tid < 2 * NN) {
        const int rr = tid >> 7;
        const int s = tid & (NN - 1);
        const int r = r0 + rr;
        const float rx = sp[r * 3 + 0], ry = sp[r * 3 + 1], rz = sp[r * 3 + 2];
        float dx0 = sp0[r * 3 + 0] - sp0[s * 3 + 0];
        float dy0 = sp0[r * 3 + 1] - sp0[s * 3 + 1];
        float dz0 = sp0[r * 3 + 2] - sp0[s * 3 + 2];
        float l0 = sqrtf(dx0 * dx0 + dy0 * dy0 + dz0 * dz0 + 1e-12f);
        float env = (l0 < 10.0f) ? 0.5f * (cosf(l0 * 0.3141592653589793f) + 1.0f) : 0.0f;
        if (s == r) env = 0.0f;

        float vx = rx - sp[s * 3 + 0];
        float vy = ry - sp[s * 3 + 1];
        float vz = rz - sp[s * 3 + 2];
        float lng = sqrtf(vx * vx + vy * vy + vz * vz + 1e-12f);
        float inv = 1.0f / lng;
        float ux = vx * inv, uy = vy * inv, uz = vz * inv;

        float tp = fminf(lng * TBL_SCALE, (float)TBL - 1.001f);
        int it = (int)tp;
        float fr = tp - (float)it;
        float a0 = env * (1.0f - fr);
        float a1 = env * fr;

        sData[rr][s] = make_float4(ux, uy, uz, a0);
        sD2[rr][s]   = make_float2(a1, __int_as_float(it));
    }
    __syncthreads();

    // ---- phase 2: per-channel accumulation; vecz load shared across rr ----
    float A[2][4];
#pragma unroll
    for (int rr = 0; rr < 2; rr++)
#pragma unroll
        for (int k = 0; k < 4; k++) A[rr][k] = 0.f;

    {
        const __half2* tb = g_tblh + (size_t)layer * TBL * 256;
        const uint2* vecz = g_veczbuf[p] + b * NN * FF;
#pragma unroll 4
        for (int s = q * 32; s < q * 32 + 32; s++) {
            uint2 vzp = vecz[s * FF + c];
            float2 v01 = unpack2(vzp.x);
            float2 v2z = unpack2(vzp.y);
#pragma unroll
            for (int rr = 0; rr < 2; rr++) {
                float4 d0 = sData[rr][s];
                float2 d1 = sD2[rr][s];
                float a0 = d0.w, a1 = d1.x;
                int it = __float_as_int(d1.y);

                uint2 w = *(const uint2*)(tb + (size_t)it * 256 + (c << 1));
                float2 f0 = unpack2(w.x);
                float2 f1 = unpack2(w.y);
                float Rw0 = fmaf(a0, f0.x, a1 * f0.y);
                float Rw1 = fmaf(a0, f1.x, a1 * f1.y);

                float f = v2z.y;
                f = fmaf(v01.x, d0.x, f);
                f = fmaf(v01.y, d0.y, f);
                f = fmaf(v2z.x, d0.z, f);

                float t1 = Rw1 * f;
                A[rr][0] = fmaf(Rw0, f, A[rr][0]);
                A[rr][1] = fmaf(t1, d0.x, A[rr][1]);
                A[rr][2] = fmaf(t1, d0.y, A[rr][2]);
                A[rr][3] = fmaf(t1, d0.z, A[rr][3]);
            }
        }
    }

    if (q > 0) {
#pragma unroll
        for (int rr = 0; rr < 2; rr++)
#pragma unroll
            for (int k = 0; k < 4; k++)
                rp[(q - 1) * 1024 + rr * 512 + k * FF + c] = A[rr][k];
    }
    __syncthreads();

    if (q == 0) {
#pragma unroll
        for (int rr = 0; rr < 2; rr++) {
            const int ro = rr * 512;
            float A0 = A[rr][0] + rp[ro + c] + rp[1024 + ro + c] + rp[2048 + ro + c];
            float A1 = A[rr][1] + rp[ro + FF + c] + rp[1024 + ro + FF + c] + rp[2048 + ro + FF + c];
            float A2 = A[rr][2] + rp[ro + 2 * FF + c] + rp[1024 + ro + 2 * FF + c] + rp[2048 + ro + 2 * FF + c];
            float A3 = A[rr][3] + rp[ro + 3 * FF + c] + rp[1024 + ro + 3 * FF + c] + rp[2048 + ro + 3 * FF + c];

            float n0 = A0 * A0;
            float n1 = A1 * A1 + A2 * A2 + A3 * A3;

            const int co = (layer * 4) * FF + c;
            float g0 = 1.f + c1w[co]      * n0 + c2w[co]      * n0 * n0 + c3w[co]      * n0 * n0 * n0;
            float g1 = 1.f + c1w[co + FF] * n1 + c2w[co + FF] * n1 * n1 + c3w[co + FF] * n1 * n1 * n1;

            sA[ro + c]          = A0 * g0;
            sA[ro + FF + c]     = A1 * g1;
            sA[ro + 2 * FF + c] = A2 * g1;
            sA[ro + 3 * FF + c] = A3 * g1;
        }
    }
    __syncthreads();

    // ---- node phase: threads [0,256) -> node r0, [256,512) -> node r0+1 ----
    const int n = tid >> 8;
    const int t2 = tid & 255;
    const int lane = t2 & 31;
    const int q8 = t2 >> 5;
    const int c4 = lane * 4;
    const float* an = sA + n * 512;
    const int bn = b * NN + r0 + n;

    {
        const float* M0 = Wmix0 + layer * FF * FF + c4;
        const float* M1 = Wmix1 + layer * FF * FF + c4;
        float4 a0v = make_float4(0.f, 0.f, 0.f, 0.f);
        float4 a1v = a0v, a2v = a0v, a3v = a0v;
#pragma unroll
        for (int kk = 0; kk < 16; kk++) {
            int k = q8 * 16 + kk;
            float4 m0 = *(const float4*)(M0 + k * FF);
            float4 m1 = *(const float4*)(M1 + k * FF);
            float aS = an[k], b0 = an[FF + k], b1 = an[2 * FF + k], b2 = an[3 * FF + k];
            a0v.x = fmaf(aS, m0.x, a0v.x); a0v.y = fmaf(aS, m0.y, a0v.y);
            a0v.z = fmaf(aS, m0.z, a0v.z); a0v.w = fmaf(aS, m0.w, a0v.w);
            a1v.x = fmaf(b0, m1.x, a1v.x); a1v.y = fmaf(b0, m1.y, a1v.y);
            a1v.z = fmaf(b0, m1.z, a1v.z); a1v.w = fmaf(b0, m1.w, a1v.w);
            a2v.x = fmaf(b1, m1.x, a2v.x); a2v.y = fmaf(b1, m1.y, a2v.y);
            a2v.z = fmaf(b1, m1.z, a2v.z); a2v.w = fmaf(b1, m1.w, a2v.w);
            a3v.x = fmaf(b2, m1.x, a3v.x); a3v.y = fmaf(b2, m1.y, a3v.y);
            a3v.z = fmaf(b2, m1.z, a3v.z); a3v.w = fmaf(b2, m1.w, a3v.w);
        }
        float* pq = rp + q8 * 1024 + n * 512;
        *(float4*)&pq[0 * FF + c4] = a0v;
        *(float4*)&pq[1 * FF + c4] = a1v;
        *(float4*)&pq[2 * FF + c4] = a2v;
        *(float4*)&pq[3 * FF + c4] = a3v;
    }
    __syncthreads();

    for (int idx = t2; idx < 512; idx += 256) {
        float s = 0.f;
#pragma unroll
        for (int qq = 0; qq < 8; qq++) s += rp[qq * 1024 + n * 512 + idx];
        sred[n * 512 + idx] = s;
    }
    __syncthreads();

    if (t2 < 32) {
        int cc = t2 & 15, hf = t2 >> 4;
        const float* G1 = Wg1 + layer * FF * 16 + cc;
        const float* sn = sred + n * 512;
        float a = 0.f;
#pragma unroll 8
        for (int kk = 0; kk < 64; kk++) {
            int k = hf * 64 + kk;
            a = fmaf(sn[k], G1[k * 16], a);
        }
        shp[n][hf][cc] = a;
    }
    __syncthreads();
    if (t2 < 16) {
        float a = shp[n][0][t2] + shp[n][1][t2];
        sh[n][t2] = a / (1.0f + expf(-a));
    }
    __syncthreads();

    if (t2 < 128) {
        const float* G2 = Wg2 + layer * 16 * FF;
        float gate = 0.f;
#pragma unroll
        for (int j = 0; j < 16; j++) gate = fmaf(sh[n][j], G2[j * FF + t2], gate);
        float w = gate * Wvout[layer * FF + t2];
        const float* sn = sred + n * 512;
        float m0 = sn[FF + t2] * w;
        float m1 = sn[2 * FF + t2] * w;
        float m2 = sn[3 * FF + t2] * w;
#pragma unroll
        for (int off = 16; off > 0; off >>= 1) {
            m0 += __shfl_down_sync(0xffffffffu, m0, off);
            m1 += __shfl_down_sync(0xffffffffu, m1, off);
            m2 += __shfl_down_sync(0xffffffffu, m2, off);
        }
        if ((t2 & 31) == 0) {
            int wp = t2 >> 5;
            rb[n][0][wp] = m0; rb[n][1][wp] = m1; rb[n][2][wp] = m2;
        }
    }
    __syncthreads();
    if (t2 < 3) {
        float pnew = sp[(r0 + n) * 3 + t2]
                   + rb[n][t2][0] + rb[n][t2][1] + rb[n][t2][2] + rb[n][t2][3];
        g_posbuf[1 - p][bn * 3 + t2] = pnew;
        if (layer == LL - 1)
            out[bn * 3 + t2] = pnew - pos_in[bn * 3 + t2];
    }

    if (layer + 1 < LL) {
        const float* W = Wnode + (layer + 1) * FF * FF + c4;
        const float* sn = sred + n * 512;
        float4 zacc = make_float4(0.f, 0.f, 0.f, 0.f);
#pragma unroll
        for (int kk = 0; kk < 16; kk++) {
            int k = q8 * 16 + kk;
            float4 w4 = *(const float4*)(W + k * FF);
            float s = sn[k];
            zacc.x = fmaf(s, w4.x, zacc.x); zacc.y = fmaf(s, w4.y, zacc.y);
            zacc.z = fmaf(s, w4.z, zacc.z); zacc.w = fmaf(s, w4.w, zacc.w);
        }
        __syncthreads();
        *(float4*)&rp[q8 * 1024 + n * 512 + c4] = zacc;
        __syncthreads();
        if (t2 < 128) {
            float s = 0.f;
#pragma unroll
            for (int qq = 0; qq < 8; qq++) s += rp[qq * 1024 + n * 512 + t2];
            zred[n][t2] = s;
        }
        __syncthreads();
    }

    if (t2 < 128) {
        const float* sn = sred + n * 512;
        float zn = (layer + 1 < LL) ? zred[n][t2] : 0.f;
        g_veczbuf[1 - p][bn * FF + t2] =
            make_uint2(pack2(sn[FF + t2], sn[2 * FF + t2]), pack2(sn[3 * FF + t2], zn));
    }
}

// ---------------------------------------------------------------------------
extern "C" void kernel_launch(void* const* d_in, const int* in_sizes, int n_in,
                              void* d_out, int out_size) {
    const float* positions     = (const float*)d_in[0];
    const int*   node_features = (const int*)d_in[1];
    const float* gf            = (const float*)d_in[2];
    const float* W_embed       = (const float*)d_in[3];
    const float* b_embed       = (const float*)d_in[4];
    const float* Wr1           = (const float*)d_in[5];
    const float* br1           = (const float*)d_in[6];
    const float* Wr2           = (const float*)d_in[7];
    const float* Wnode         = (const float*)d_in[8];
    const float* c1w           = (const float*)d_in[9];
    const float* c2w           = (const float*)d_in[10];
    const float* c3w           = (const float*)d_in[11];
    const float* Wmix0         = (const float*)d_in[12];
    const float* Wmix1         = (const float*)d_in[13];
    const float* Wg1           = (const float*)d_in[14];
    const float* Wg2           = (const float*)d_in[15];
    const float* Wvout         = (const float*)d_in[16];
    float* out = (float*)d_out;

    k_prep<<<TBLK * LL + BB * NN, 128>>>(Wr1, br1, Wr2, positions, node_features,
                                         gf, W_embed, b_embed, Wnode);
    for (int i = 0; i < LL; i++)
        k_layer<<<dim3(NN / 2, BB), dim3(128, 4)>>>(positions, c1w, c2w, c3w,
                                                    Wmix0, Wmix1, Wg1, Wg2, Wvout,
                                                    Wnode, out, i);
}

// round 13
// speedup vs baseline: 1.7211x; 1.1169x over previous
#include <cuda_runtime.h>
#include <cuda_fp16.h>
#include <math.h>

#define BB 4
#define NN 128
#define FF 128
#define SS 5
#define TGLOB 32
#define LL 2
#define TBL 512
#define LMAX 16.0f
#define TBL_SCALE (TBL / LMAX)
#define TBLK (TBL / 8)          /* table blocks per layer = 64 */

// ---------------- persistent scratch (device globals; no allocation) ------
__device__ float g_posbuf[2][BB * NN * 3];
__device__ uint2 g_veczbuf[2][BB * NN * FF];      // half2(v0,v1), half2(v2,z)
__device__ __half2 g_tblh[LL * TBL * 256];        // (w_t,w_{t+1}) pairs, ell 0..1
                                                  // ell0 pre-scaled by 1/16,
                                                  // ell1 by sqrt(3)/16

__device__ __forceinline__ unsigned pack2(float a, float b) {
    __half2 h = __floats2half2_rn(a, b);
    return *reinterpret_cast<unsigned*>(&h);
}
__device__ __forceinline__ float2 unpack2(unsigned u) {
    __half2 h = *reinterpret_cast<__half2*>(&u);
    return __half22float2(h);
}

// ---------------- fused prep: radial tables (ell<=1) + embed/init ---------
// 256 threads. Table blocks: m-loop split 2-way. Init blocks: 2 nodes each,
// z-GEMV in (32 lanes x 8-way k) float4 shape with shared Wnode loads.
__global__ __launch_bounds__(256) void k_prep(const float* __restrict__ Wr1,
                                              const float* __restrict__ br1,
                                              const float* __restrict__ Wr2,
                                              const float* __restrict__ positions,
                                              const int* __restrict__ node_features,
                                              const float* __restrict__ gf,
                                              const float* __restrict__ W_embed,
                                              const float* __restrict__ b_embed,
                                              const float* __restrict__ Wnode) {
    const int tid = threadIdx.x;
    if (blockIdx.x < TBLK * LL) {
        // ---- table part: 8 pair-rows (9 sample rows), m split 2-way ----
        const int i = blockIdx.x / TBLK;
        const int tb0 = (blockIdx.x % TBLK) * 8;
        const int c = tid & 127;
        const int half = tid >> 7;
        __shared__ float h[9][64];
        __shared__ float redt[9][2][128];
        if (tid < 64) {
            float w1 = Wr1[i * 64 + tid];
            float b1 = br1[i * 64 + tid];
#pragma unroll
            for (int j = 0; j < 9; j++) {
                float lng = (float)(tb0 + j) * (LMAX / (float)TBL);
                float p = lng * w1 + b1;
                h[j][tid] = p / (1.0f + expf(-p));
            }
        }
        __syncthreads();
        const float* W = Wr2 + i * 64 * 512 + c;
        float acc[9][2];
#pragma unroll
        for (int j = 0; j < 9; j++) { acc[j][0] = 0.f; acc[j][1] = 0.f; }
#pragma unroll 4
        for (int mm = 0; mm < 32; mm++) {
            int m = half * 32 + mm;
            float w0 = W[m * 512 + 0];
            float w1v = W[m * 512 + 128];
#pragma unroll
            for (int j = 0; j < 9; j++) {
                float hm = h[j][m];
                acc[j][0] = fmaf(hm, w0, acc[j][0]);
                acc[j][1] = fmaf(hm, w1v, acc[j][1]);
            }
        }
        if (half == 1) {
#pragma unroll
            for (int j = 0; j < 9; j++) {
                redt[j][0][c] = acc[j][0];
                redt[j][1][c] = acc[j][1];
            }
        }
        __syncthreads();
        if (half == 0) {
            const float sc0 = 1.0f / 16.0f;
            const float sc1 = 1.7320508075688772f / 16.0f;
            float f0[9], f1[9];
#pragma unroll
            for (int j = 0; j < 9; j++) {
                f0[j] = (acc[j][0] + redt[j][0][c]) * sc0;
                f1[j] = (acc[j][1] + redt[j][1][c]) * sc1;
            }
#pragma unroll
            for (int j = 0; j < 8; j++) {
                __half2* dst = g_tblh + ((size_t)i * TBL + tb0 + j) * 256 + c * 2;
                dst[0] = __float22half2_rn(make_float2(f0[j], f0[j + 1]));
                dst[1] = __float22half2_rn(make_float2(f1[j], f1[j + 1]));
            }
        }
    } else {
        // ---- init part: 2 nodes per block ----
        const int bn0 = (blockIdx.x - TBLK * LL) * 2;
        const int n = tid >> 7;
        const int c = tid & 127;
        const int bn = bn0 + n;
        const int b = bn / NN;
        __shared__ float srow[2][FF];
        __shared__ float part[8][2 * FF];

        int nf = node_features[bn];
        float s = W_embed[(nf - 1) * FF + c] + b_embed[c];
#pragma unroll 8
        for (int t = 0; t < TGLOB; t++)
            s = fmaf(gf[b * TGLOB + t], W_embed[(SS + t) * FF + c], s);
        srow[n][c] = s;
        if (c < 3) g_posbuf[0][bn * 3 + c] = positions[bn * 3 + c];
        __syncthreads();

        // z GEMV: lane owns 4 channels, q8 = 8-way k split, both nodes share w4
        const int lane = tid & 31;
        const int q8 = tid >> 5;
        const int c4 = lane * 4;
        const float* W = Wnode + c4;
        float4 z0 = make_float4(0.f, 0.f, 0.f, 0.f);
        float4 z1 = z0;
#pragma unroll
        for (int kk = 0; kk < 16; kk++) {
            int k = q8 * 16 + kk;
            float4 w4 = *(const float4*)(W + k * FF);
            float s0 = srow[0][k], s1 = srow[1][k];
            z0.x = fmaf(s0, w4.x, z0.x); z0.y = fmaf(s0, w4.y, z0.y);
            z0.z = fmaf(s0, w4.z, z0.z); z0.w = fmaf(s0, w4.w, z0.w);
            z1.x = fmaf(s1, w4.x, z1.x); z1.y = fmaf(s1, w4.y, z1.y);
            z1.z = fmaf(s1, w4.z, z1.z); z1.w = fmaf(s1, w4.w, z1.w);
        }
        *(float4*)&part[q8][c4]      = z0;
        *(float4*)&part[q8][FF + c4] = z1;
        __syncthreads();

        float zsum = 0.f;
#pragma unroll
        for (int qq = 0; qq < 8; qq++) zsum += part[qq][tid];
        g_veczbuf[0][(bn0 + n) * FF + c] = make_uint2(pack2(0.f, 0.f), pack2(0.f, zsum));
    }
}

// ---------------- fused layer: msg (2 receivers) + node update ------------
// grid (NN/2, BB); blockDim (128,4). A4 passes through smem only.
__global__ __launch_bounds__(512, 2) void k_layer(const float* __restrict__ pos_in,
                                                  const float* __restrict__ c1w,
                                                  const float* __restrict__ c2w,
                                                  const float* __restrict__ c3w,
                                                  const float* __restrict__ Wmix0,
                                                  const float* __restrict__ Wmix1,
                                                  const float* __restrict__ Wg1,
                                                  const float* __restrict__ Wg2,
                                                  const float* __restrict__ Wvout,
                                                  const float* __restrict__ Wnode,
                                                  float* __restrict__ out,
                                                  int layer) {
    const int r0 = blockIdx.x * 2;
    const int b = blockIdx.y;
    const int c = threadIdx.x;
    const int q = threadIdx.y;
    const int tid = q * 128 + c;
    const int p = layer & 1;

    __shared__ float sp[NN * 3];
    __shared__ float sp0[NN * 3];
    __shared__ float4 sData[2][NN];
    __shared__ float2 sD2[2][NN];
    __shared__ float rp[8 * 1024];   // msg: red[3][2][512]; node: part[8][2*512]
    __shared__ float sA[2 * 512];
    __shared__ float sred[2 * 512];
    __shared__ float shp[2][2][16];
    __shared__ float sh[2][16];
    __shared__ float rb[2][3][4];
    __shared__ float zred[2][FF];

    for (int idx = tid; idx < NN * 3; idx += 512) {
        sp[idx]  = g_posbuf[p][b * NN * 3 + idx];
        sp0[idx] = pos_in[b * NN * 3 + idx];
    }
    __syncthreads();

    // ---- phase 1: per-(receiver, sender) geometry, 256 threads ----
    if (tid < 2 * NN) {
        const int rr = tid >> 7;
        const int s = tid & (NN - 1);
        const int r = r0 + rr;
        const float rx = sp[r * 3 + 0], ry = sp[r * 3 + 1], rz = sp[r * 3 + 2];
        float dx0 = sp0[r * 3 + 0] - sp0[s * 3 + 0];
        float dy0 = sp0[r * 3 + 1] - sp0[s * 3 + 1];
        float dz0 = sp0[r * 3 + 2] - sp0[s * 3 + 2];
        float l0 = sqrtf(dx0 * dx0 + dy0 * dy0 + dz0 * dz0 + 1e-12f);
        float env = (l0 < 10.0f) ? 0.5f * (cosf(l0 * 0.3141592653589793f) + 1.0f) : 0.0f;
        if (s == r) env = 0.0f;

        float vx = rx - sp[s * 3 + 0];
        float vy = ry - sp[s * 3 + 1];
        float vz = rz - sp[s * 3 + 2];
        float lng = sqrtf(vx * vx + vy * vy + vz * vz + 1e-12f);
        float inv = 1.0f / lng;
        float ux = vx * inv, uy = vy * inv, uz = vz * inv;

        float tp = fminf(lng * TBL_SCALE, (float)TBL - 1.001f);
        int it = (int)tp;
        float fr = tp - (float)it;
        float a0 = env * (1.0f - fr);
        float a1 = env * fr;

        sData[rr][s] = make_float4(ux, uy, uz, a0);
        sD2[rr][s]   = make_float2(a1, __int_as_float(it));
    }
    __syncthreads();

    // ---- phase 2: per-channel accumulation; vecz load shared across rr ----
    float A[2][4];
#pragma unroll
    for (int rr = 0; rr < 2; rr++)
#pragma unroll
        for (int k = 0; k < 4; k++) A[rr][k] = 0.f;

    {
        const __half2* tb = g_tblh + (size_t)layer * TBL * 256;
        const uint2* vecz = g_veczbuf[p] + b * NN * FF;
#pragma unroll 4
        for (int s = q * 32; s < q * 32 + 32; s++) {
            uint2 vzp = vecz[s * FF + c];
            float2 v01 = unpack2(vzp.x);
            float2 v2z = unpack2(vzp.y);
#pragma unroll
            for (int rr = 0; rr < 2; rr++) {
                float4 d0 = sData[rr][s];
                float2 d1 = sD2[rr][s];
                float a0 = d0.w, a1 = d1.x;
                int it = __float_as_int(d1.y);

                uint2 w = *(const uint2*)(tb + (size_t)it * 256 + (c << 1));
                float2 f0 = unpack2(w.x);
                float2 f1 = unpack2(w.y);
                float Rw0 = fmaf(a0, f0.x, a1 * f0.y);
                float Rw1 = fmaf(a0, f1.x, a1 * f1.y);

                float f = v2z.y;
                f = fmaf(v01.x, d0.x, f);
                f = fmaf(v01.y, d0.y, f);
                f = fmaf(v2z.x, d0.z, f);

                float t1 = Rw1 * f;
                A[rr][0] = fmaf(Rw0, f, A[rr][0]);
                A[rr][1] = fmaf(t1, d0.x, A[rr][1]);
                A[rr][2] = fmaf(t1, d0.y, A[rr][2]);
                A[rr][3] = fmaf(t1, d0.z, A[rr][3]);
            }
        }
    }

    if (q > 0) {
#pragma unroll
        for (int rr = 0; rr < 2; rr++)
#pragma unroll
            for (int k = 0; k < 4; k++)
                rp[(q - 1) * 1024 + rr * 512 + k * FF + c] = A[rr][k];
    }
    __syncthreads();

    if (q == 0) {
#pragma unroll
        for (int rr = 0; rr < 2; rr++) {
            const int ro = rr * 512;
            float A0 = A[rr][0] + rp[ro + c] + rp[1024 + ro + c] + rp[2048 + ro + c];
            float A1 = A[rr][1] + rp[ro + FF + c] + rp[1024 + ro + FF + c] + rp[2048 + ro + FF + c];
            float A2 = A[rr][2] + rp[ro + 2 * FF + c] + rp[1024 + ro + 2 * FF + c] + rp[2048 + ro + 2 * FF + c];
            float A3 = A[rr][3] + rp[ro + 3 * FF + c] + rp[1024 + ro + 3 * FF + c] + rp[2048 + ro + 3 * FF + c];

            float n0 = A0 * A0;
            float n1 = A1 * A1 + A2 * A2 + A3 * A3;

            const int co = (layer * 4) * FF + c;
            float g0 = 1.f + c1w[co]      * n0 + c2w[co]      * n0 * n0 + c3w[co]      * n0 * n0 * n0;
            float g1 = 1.f + c1w[co + FF] * n1 + c2w[co + FF] * n1 * n1 + c3w[co + FF] * n1 * n1 * n1;

            sA[ro + c]          = A0 * g0;
            sA[ro + FF + c]     = A1 * g1;
            sA[ro + 2 * FF + c] = A2 * g1;
            sA[ro + 3 * FF + c] = A3 * g1;
        }
    }
    __syncthreads();

    // ---- node phase: threads [0,256) -> node r0, [256,512) -> node r0+1 ----
    const int n = tid >> 8;
    const int t2 = tid & 255;
    const int lane = t2 & 31;
    const int q8 = t2 >> 5;
    const int c4 = lane * 4;
    const float* an = sA + n * 512;
    const int bn = b * NN + r0 + n;

    {
        const float* M0 = Wmix0 + layer * FF * FF + c4;
        const float* M1 = Wmix1 + layer * FF * FF + c4;
        float4 a0v = make_float4(0.f, 0.f, 0.f, 0.f);
        float4 a1v = a0v, a2v = a0v, a3v = a0v;
#pragma unroll
        for (int kk = 0; kk < 16; kk++) {
            int k = q8 * 16 + kk;
            float4 m0 = *(const float4*)(M0 + k * FF);
            float4 m1 = *(const float4*)(M1 + k * FF);
            float aS = an[k], b0 = an[FF + k], b1 = an[2 * FF + k], b2 = an[3 * FF + k];
            a0v.x = fmaf(aS, m0.x, a0v.x); a0v.y = fmaf(aS, m0.y, a0v.y);
            a0v.z = fmaf(aS, m0.z, a0v.z); a0v.w = fmaf(aS, m0.w, a0v.w);
            a1v.x = fmaf(b0, m1.x, a1v.x); a1v.y = fmaf(b0, m1.y, a1v.y);
            a1v.z = fmaf(b0, m1.z, a1v.z); a1v.w = fmaf(b0, m1.w, a1v.w);
            a2v.x = fmaf(b1, m1.x, a2v.x); a2v.y = fmaf(b1, m1.y, a2v.y);
            a2v.z = fmaf(b1, m1.z, a2v.z); a2v.w = fmaf(b1, m1.w, a2v.w);
            a3v.x = fmaf(b2, m1.x, a3v.x); a3v.y = fmaf(b2, m1.y, a3v.y);
            a3v.z = fmaf(b2, m1.z, a3v.z); a3v.w = fmaf(b2, m1.w, a3v.w);
        }
        float* pq = rp + q8 * 1024 + n * 512;
        *(float4*)&pq[0 * FF + c4] = a0v;
        *(float4*)&pq[1 * FF + c4] = a1v;
        *(float4*)&pq[2 * FF + c4] = a2v;
        *(float4*)&pq[3 * FF + c4] = a3v;
    }
    __syncthreads();

    for (int idx = t2; idx < 512; idx += 256) {
        float s = 0.f;
#pragma unroll
        for (int qq = 0; qq < 8; qq++) s += rp[qq * 1024 + n * 512 + idx];
        sred[n * 512 + idx] = s;
    }
    __syncthreads();

    if (t2 < 32) {
        int cc = t2 & 15, hf = t2 >> 4;
        const float* G1 = Wg1 + layer * FF * 16 + cc;
        const float* sn = sred + n * 512;
        float a = 0.f;
#pragma unroll 8
        for (int kk = 0; kk < 64; kk++) {
            int k = hf * 64 + kk;
            a = fmaf(sn[k], G1[k * 16], a);
        }
        shp[n][hf][cc] = a;
    }
    __syncthreads();
    if (t2 < 16) {
        float a = shp[n][0][t2] + shp[n][1][t2];
        sh[n][t2] = a / (1.0f + expf(-a));
    }
    __syncthreads();

    if (t2 < 128) {
        const float* G2 = Wg2 + layer * 16 * FF;
        float gate = 0.f;
#pragma unroll
        for (int j = 0; j < 16; j++) gate = fmaf(sh[n][j], G2[j * FF + t2], gate);
        float w = gate * Wvout[layer * FF + t2];
        const float* sn = sred + n * 512;
        float m0 = sn[FF + t2] * w;
        float m1 = sn[2 * FF + t2] * w;
        float m2 = sn[3 * FF + t2] * w;
#pragma unroll
        for (int off = 16; off > 0; off >>= 1) {
            m0 += __shfl_down_sync(0xffffffffu, m0, off);
            m1 += __shfl_down_sync(0xffffffffu, m1, off);
            m2 += __shfl_down_sync(0xffffffffu, m2, off);
        }
        if ((t2 & 31) == 0) {
            int wp = t2 >> 5;
            rb[n][0][wp] = m0; rb[n][1][wp] = m1; rb[n][2][wp] = m2;
        }
    }
    __syncthreads();
    if (t2 < 3) {
        float pnew = sp[(r0 + n) * 3 + t2]
                   + rb[n][t2][0] + rb[n][t2][1] + rb[n][t2][2] + rb[n][t2][3];
        g_posbuf[1 - p][bn * 3 + t2] = pnew;
        if (layer == LL - 1)
            out[bn * 3 + t2] = pnew - pos_in[bn * 3 + t2];
    }

    if (layer + 1 < LL) {
        const float* W = Wnode + (layer + 1) * FF * FF + c4;
        const float* sn = sred + n * 512;
        float4 zacc = make_float4(0.f, 0.f, 0.f, 0.f);
#pragma unroll
        for (int kk = 0; kk < 16; kk++) {
            int k = q8 * 16 + kk;
            float4 w4 = *(const float4*)(W + k * FF);
            float s = sn[k];
            zacc.x = fmaf(s, w4.x, zacc.x); zacc.y = fmaf(s, w4.y, zacc.y);
            zacc.z = fmaf(s, w4.z, zacc.z); zacc.w = fmaf(s, w4.w, zacc.w);
        }
        __syncthreads();
        *(float4*)&rp[q8 * 1024 + n * 512 + c4] = zacc;
        __syncthreads();
        if (t2 < 128) {
            float s = 0.f;
#pragma unroll
            for (int qq = 0; qq < 8; qq++) s += rp[qq * 1024 + n * 512 + t2];
            zred[n][t2] = s;
        }
        __syncthreads();
    }

    if (t2 < 128) {
        const float* sn = sred + n * 512;
        float zn = (layer + 1 < LL) ? zred[n][t2] : 0.f;
        g_veczbuf[1 - p][bn * FF + t2] =
            make_uint2(pack2(sn[FF + t2], sn[2 * FF + t2]), pack2(sn[3 * FF + t2], zn));
    }
}

// ---------------------------------------------------------------------------
extern "C" void kernel_launch(void* const* d_in, const int* in_sizes, int n_in,
                              void* d_out, int out_size) {
    const float* positions     = (const float*)d_in[0];
    const int*   node_features = (const int*)d_in[1];
    const float* gf            = (const float*)d_in[2];
    const float* W_embed       = (const float*)d_in[3];
    const float* b_embed       = (const float*)d_in[4];
    const float* Wr1           = (const float*)d_in[5];
    const float* br1           = (const float*)d_in[6];
    const float* Wr2           = (const float*)d_in[7];
    const float* Wnode         = (const float*)d_in[8];
    const float* c1w           = (const float*)d_in[9];
    const float* c2w           = (const float*)d_in[10];
    const float* c3w           = (const float*)d_in[11];
    const float* Wmix0         = (const float*)d_in[12];
    const float* Wmix1         = (const float*)d_in[13];
    const float* Wg1           = (const float*)d_in[14];
    const float* Wg2           = (const float*)d_in[15];
    const float* Wvout         = (const float*)d_in[16];
    float* out = (float*)d_out;

    k_prep<<<TBLK * LL + BB * NN / 2, 256>>>(Wr1, br1, Wr2, positions, node_features,
                                             gf, W_embed, b_embed, Wnode);
    for (int i = 0; i < LL; i++)
        k_layer<<<dim3(NN / 2, BB), dim3(128, 4)>>>(positions, c1w, c2w, c3w,
                                                    Wmix0, Wmix1, Wg1, Wg2, Wvout,
                                                    Wnode, out, i);
}

// round 14
// speedup vs baseline: 1.7246x; 1.0020x over previous
#include <cuda_runtime.h>
#include <cuda_fp16.h>
#include <math.h>

#define BB 4
#define NN 128
#define FF 128
#define SS 5
#define TGLOB 32
#define LL 2
#define TBL 256
#define LMAX 16.0f
#define TBL_SCALE (TBL / LMAX)
#define TBLK (TBL / 8)          /* table blocks per layer = 32 */

// ---------------- persistent scratch (device globals; no allocation) ------
__device__ float g_posbuf[2][BB * NN * 3];
__device__ uint2 g_veczbuf[2][BB * NN * FF];      // half2(v0,v1), half2(v2,z)
__device__ __half2 g_tblh[LL * TBL * 256];        // (w_t,w_{t+1}) pairs, ell 0..1
                                                  // ell0 pre-scaled by 1/16,
                                                  // ell1 by sqrt(3)/16

__device__ __forceinline__ unsigned pack2(float a, float b) {
    __half2 h = __floats2half2_rn(a, b);
    return *reinterpret_cast<unsigned*>(&h);
}
__device__ __forceinline__ float2 unpack2(unsigned u) {
    __half2 h = *reinterpret_cast<__half2*>(&u);
    return __half22float2(h);
}

// ---------------- fused prep: radial tables (ell<=1) + embed/init ---------
// 512 threads. Table blocks: m-loop split 4-way. Init blocks: 4 nodes each,
// z-GEMV with 4-way k split and Wnode float4 rows shared across nodes.
__global__ __launch_bounds__(512) void k_prep(const float* __restrict__ Wr1,
                                              const float* __restrict__ br1,
                                              const float* __restrict__ Wr2,
                                              const float* __restrict__ positions,
                                              const int* __restrict__ node_features,
                                              const float* __restrict__ gf,
                                              const float* __restrict__ W_embed,
                                              const float* __restrict__ b_embed,
                                              const float* __restrict__ Wnode) {
    const int tid = threadIdx.x;
    if (blockIdx.x < TBLK * LL) {
        // ---- table part: 8 pair-rows (9 sample rows), m split 4-way ----
        const int i = blockIdx.x / TBLK;
        const int tb0 = (blockIdx.x % TBLK) * 8;
        const int c = tid & 127;
        const int qm = tid >> 7;                 // 0..3
        __shared__ float h[9][64];
        __shared__ float redt[3][9][2][128];     // partials from qm=1..3
        if (tid < 64) {
            float w1 = Wr1[i * 64 + tid];
            float b1 = br1[i * 64 + tid];
#pragma unroll
            for (int j = 0; j < 9; j++) {
                float lng = (float)(tb0 + j) * (LMAX / (float)TBL);
                float p = lng * w1 + b1;
                h[j][tid] = p / (1.0f + expf(-p));
            }
        }
        __syncthreads();
        const float* W = Wr2 + i * 64 * 512 + c;
        float acc[9][2];
#pragma unroll
        for (int j = 0; j < 9; j++) { acc[j][0] = 0.f; acc[j][1] = 0.f; }
#pragma unroll 4
        for (int mm = 0; mm < 16; mm++) {
            int m = qm * 16 + mm;
            float w0 = W[m * 512 + 0];
            float w1v = W[m * 512 + 128];
#pragma unroll
            for (int j = 0; j < 9; j++) {
                float hm = h[j][m];
                acc[j][0] = fmaf(hm, w0, acc[j][0]);
                acc[j][1] = fmaf(hm, w1v, acc[j][1]);
            }
        }
        if (qm > 0) {
#pragma unroll
            for (int j = 0; j < 9; j++) {
                redt[qm - 1][j][0][c] = acc[j][0];
                redt[qm - 1][j][1][c] = acc[j][1];
            }
        }
        __syncthreads();
        if (qm == 0) {
            const float sc0 = 1.0f / 16.0f;
            const float sc1 = 1.7320508075688772f / 16.0f;
            float f0[9], f1[9];
#pragma unroll
            for (int j = 0; j < 9; j++) {
                f0[j] = (acc[j][0] + redt[0][j][0][c] + redt[1][j][0][c] + redt[2][j][0][c]) * sc0;
                f1[j] = (acc[j][1] + redt[0][j][1][c] + redt[1][j][1][c] + redt[2][j][1][c]) * sc1;
            }
#pragma unroll
            for (int j = 0; j < 8; j++) {
                __half2* dst = g_tblh + ((size_t)i * TBL + tb0 + j) * 256 + c * 2;
                dst[0] = __float22half2_rn(make_float2(f0[j], f0[j + 1]));
                dst[1] = __float22half2_rn(make_float2(f1[j], f1[j + 1]));
            }
        }
    } else {
        // ---- init part: 4 nodes per block ----
        const int bn0 = (blockIdx.x - TBLK * LL) * 4;
        const int n = tid >> 7;                  // 0..3
        const int c = tid & 127;
        const int bn = bn0 + n;
        const int b = bn / NN;
        __shared__ float srow[4][FF];
        __shared__ float part[4][4][FF];         // [k-quarter][node][c]

        int nf = node_features[bn];
        float s = W_embed[(nf - 1) * FF + c] + b_embed[c];
#pragma unroll 8
        for (int t = 0; t < TGLOB; t++)
            s = fmaf(gf[b * TGLOB + t], W_embed[(SS + t) * FF + c], s);
        srow[n][c] = s;
        if (c < 3) g_posbuf[0][bn * 3 + c] = positions[bn * 3 + c];
        __syncthreads();

        // z GEMV: lane owns 4 channels; grp = nz*4 + q4 (node, k-quarter)
        const int lane = tid & 31;
        const int grp = tid >> 5;                // 0..15
        const int nz = grp >> 2;                 // node 0..3
        const int q4 = grp & 3;                  // k quarter 0..3
        const int c4 = lane * 4;
        const float* W = Wnode + c4;
        float4 z = make_float4(0.f, 0.f, 0.f, 0.f);
#pragma unroll
        for (int kk = 0; kk < 32; kk++) {
            int k = q4 * 32 + kk;
            float4 w4 = *(const float4*)(W + k * FF);
            float sv = srow[nz][k];
            z.x = fmaf(sv, w4.x, z.x); z.y = fmaf(sv, w4.y, z.y);
            z.z = fmaf(sv, w4.z, z.z); z.w = fmaf(sv, w4.w, z.w);
        }
        __syncthreads();
        *(float4*)&part[q4][nz][c4] = z;
        __syncthreads();

        float zsum = part[0][n][c] + part[1][n][c] + part[2][n][c] + part[3][n][c];
        g_veczbuf[0][bn * FF + c] = make_uint2(pack2(0.f, 0.f), pack2(0.f, zsum));
    }
}

// ---------------- fused layer: msg (2 receivers) + node update ------------
// grid (NN/2, BB); blockDim (128,4). A4 passes through smem only.
__global__ __launch_bounds__(512, 2) void k_layer(const float* __restrict__ pos_in,
                                                  const float* __restrict__ c1w,
                                                  const float* __restrict__ c2w,
                                                  const float* __restrict__ c3w,
                                                  const float* __restrict__ Wmix0,
                                                  const float* __restrict__ Wmix1,
                                                  const float* __restrict__ Wg1,
                                                  const float* __restrict__ Wg2,
                                                  const float* __restrict__ Wvout,
                                                  const float* __restrict__ Wnode,
                                                  float* __restrict__ out,
                                                  int layer) {
    const int r0 = blockIdx.x * 2;
    const int b = blockIdx.y;
    const int c = threadIdx.x;
    const int q = threadIdx.y;
    const int tid = q * 128 + c;
    const int p = layer & 1;

    __shared__ float sp[NN * 3];
    __shared__ float sp0[NN * 3];
    __shared__ float4 sData[2][NN];
    __shared__ float2 sD2[2][NN];
    __shared__ float rp[8 * 1024];   // msg: red[3][2][512]; node: part[8][2*512]
    __shared__ float sA[2 * 512];
    __shared__ float sred[2 * 512];
    __shared__ float shp[2][2][16];
    __shared__ float sh[2][16];
    __shared__ float rb[2][3][4];
    __shared__ float zred[2][FF];

    for (int idx = tid; idx < NN * 3; idx += 512) {
        sp[idx]  = g_posbuf[p][b * NN * 3 + idx];
        sp0[idx] = pos_in[b * NN * 3 + idx];
    }
    __syncthreads();

    // ---- phase 1: per-(receiver, sender) geometry, 256 threads ----
    if (tid < 2 * NN) {
        const int rr = tid >> 7;
        const int s = tid & (NN - 1);
        const int r = r0 + rr;
        const float rx = sp[r * 3 + 0], ry = sp[r * 3 + 1], rz = sp[r * 3 + 2];
        float dx0 = sp0[r * 3 + 0] - sp0[s * 3 + 0];
        float dy0 = sp0[r * 3 + 1] - sp0[s * 3 + 1];
        float dz0 = sp0[r * 3 + 2] - sp0[s * 3 + 2];
        float l0 = sqrtf(dx0 * dx0 + dy0 * dy0 + dz0 * dz0 + 1e-12f);
        float env = (l0 < 10.0f) ? 0.5f * (cosf(l0 * 0.3141592653589793f) + 1.0f) : 0.0f;
        if (s == r) env = 0.0f;

        float vx = rx - sp[s * 3 + 0];
        float vy = ry - sp[s * 3 + 1];
        float vz = rz - sp[s * 3 + 2];
        float lng = sqrtf(vx * vx + vy * vy + vz * vz + 1e-12f);
        float inv = 1.0f / lng;
        float ux = vx * inv, uy = vy * inv, uz = vz * inv;

        float tp = fminf(lng * TBL_SCALE, (float)TBL - 1.001f);
        int it = (int)tp;
        float fr = tp - (float)it;
        float a0 = env * (1.0f - fr);
        float a1 = env * fr;

        sData[rr][s] = make_float4(ux, uy, uz, a0);
        sD2[rr][s]   = make_float2(a1, __int_as_float(it));
    }
    __syncthreads();

    // ---- phase 2: per-channel accumulation; vecz load shared across rr ----
    float A[2][4];
#pragma unroll
    for (int rr = 0; rr < 2; rr++)
#pragma unroll
        for (int k = 0; k < 4; k++) A[rr][k] = 0.f;

    {
        const __half2* tb = g_tblh + (size_t)layer * TBL * 256;
        const uint2* vecz = g_veczbuf[p] + b * NN * FF;
#pragma unroll 4
        for (int s = q * 32; s < q * 32 + 32; s++) {
            uint2 vzp = vecz[s * FF + c];
            float2 v01 = unpack2(vzp.x);
            float2 v2z = unpack2(vzp.y);
#pragma unroll
            for (int rr = 0; rr < 2; rr++) {
                float4 d0 = sData[rr][s];
                float2 d1 = sD2[rr][s];
                float a0 = d0.w, a1 = d1.x;
                int it = __float_as_int(d1.y);

                uint2 w = *(const uint2*)(tb + (size_t)it * 256 + (c << 1));
                float2 f0 = unpack2(w.x);
                float2 f1 = unpack2(w.y);
                float Rw0 = fmaf(a0, f0.x, a1 * f0.y);
                float Rw1 = fmaf(a0, f1.x, a1 * f1.y);

                float f = v2z.y;
                f = fmaf(v01.x, d0.x, f);
                f = fmaf(v01.y, d0.y, f);
                f = fmaf(v2z.x, d0.z, f);

                float t1 = Rw1 * f;
                A[rr][0] = fmaf(Rw0, f, A[rr][0]);
                A[rr][1] = fmaf(t1, d0.x, A[rr][1]);
                A[rr][2] = fmaf(t1, d0.y, A[rr][2]);
                A[rr][3] = fmaf(t1, d0.z, A[rr][3]);
            }
        }
    }

    if (q > 0) {
#pragma unroll
        for (int rr = 0; rr < 2; rr++)
#pragma unroll
            for (int k = 0; k < 4; k++)
                rp[(q - 1) * 1024 + rr * 512 + k * FF + c] = A[rr][k];
    }
    __syncthreads();

    if (q == 0) {
#pragma unroll
        for (int rr = 0; rr < 2; rr++) {
            const int ro = rr * 512;
            float A0 = A[rr][0] + rp[ro + c] + rp[1024 + ro + c] + rp[2048 + ro + c];
            float A1 = A[rr][1] + rp[ro + FF + c] + rp[1024 + ro + FF + c] + rp[2048 + ro + FF + c];
            float A2 = A[rr][2] + rp[ro + 2 * FF + c] + rp[1024 + ro + 2 * FF + c] + rp[2048 + ro + 2 * FF + c];
            float A3 = A[rr][3] + rp[ro + 3 * FF + c] + rp[1024 + ro + 3 * FF + c] + rp[2048 + ro + 3 * FF + c];

            float n0 = A0 * A0;
            float n1 = A1 * A1 + A2 * A2 + A3 * A3;

            const int co = (layer * 4) * FF + c;
            float g0 = 1.f + c1w[co]      * n0 + c2w[co]      * n0 * n0 + c3w[co]      * n0 * n0 * n0;
            float g1 = 1.f + c1w[co + FF] * n1 + c2w[co + FF] * n1 * n1 + c3w[co + FF] * n1 * n1 * n1;

            sA[ro + c]          = A0 * g0;
            sA[ro + FF + c]     = A1 * g1;
            sA[ro + 2 * FF + c] = A2 * g1;
            sA[ro + 3 * FF + c] = A3 * g1;
        }
    }
    __syncthreads();

    // ---- node phase: threads [0,256) -> node r0, [256,512) -> node r0+1 ----
    const int n = tid >> 8;
    const int t2 = tid & 255;
    const int lane = t2 & 31;
    const int q8 = t2 >> 5;
    const int c4 = lane * 4;
    const float* an = sA + n * 512;
    const int bn = b * NN + r0 + n;

    {
        const float* M0 = Wmix0 + layer * FF * FF + c4;
        const float* M1 = Wmix1 + layer * FF * FF + c4;
        float4 a0v = make_float4(0.f, 0.f, 0.f, 0.f);
        float4 a1v = a0v, a2v = a0v, a3v = a0v;
#pragma unroll
        for (int kk = 0; kk < 16; kk++) {
            int k = q8 * 16 + kk;
            float4 m0 = *(const float4*)(M0 + k * FF);
            float4 m1 = *(const float4*)(M1 + k * FF);
            float aS = an[k], b0 = an[FF + k], b1 = an[2 * FF + k], b2 = an[3 * FF + k];
            a0v.x = fmaf(aS, m0.x, a0v.x); a0v.y = fmaf(aS, m0.y, a0v.y);
            a0v.z = fmaf(aS, m0.z, a0v.z); a0v.w = fmaf(aS, m0.w, a0v.w);
            a1v.x = fmaf(b0, m1.x, a1v.x); a1v.y = fmaf(b0, m1.y, a1v.y);
            a1v.z = fmaf(b0, m1.z, a1v.z); a1v.w = fmaf(b0, m1.w, a1v.w);
            a2v.x = fmaf(b1, m1.x, a2v.x); a2v.y = fmaf(b1, m1.y, a2v.y);
            a2v.z = fmaf(b1, m1.z, a2v.z); a2v.w = fmaf(b1, m1.w, a2v.w);
            a3v.x = fmaf(b2, m1.x, a3v.x); a3v.y = fmaf(b2, m1.y, a3v.y);
            a3v.z = fmaf(b2, m1.z, a3v.z); a3v.w = fmaf(b2, m1.w, a3v.w);
        }
        float* pq = rp + q8 * 1024 + n * 512;
        *(float4*)&pq[0 * FF + c4] = a0v;
        *(float4*)&pq[1 * FF + c4] = a1v;
        *(float4*)&pq[2 * FF + c4] = a2v;
        *(float4*)&pq[3 * FF + c4] = a3v;
    }
    __syncthreads();

    for (int idx = t2; idx < 512; idx += 256) {
        float s = 0.f;
#pragma unroll
        for (int qq = 0; qq < 8; qq++) s += rp[qq * 1024 + n * 512 + idx];
        sred[n * 512 + idx] = s;
    }
    __syncthreads();

    if (t2 < 32) {
        int cc = t2 & 15, hf = t2 >> 4;
        const float* G1 = Wg1 + layer * FF * 16 + cc;
        const float* sn = sred + n * 512;
        float a = 0.f;
#pragma unroll 8
        for (int kk = 0; kk < 64; kk++) {
            int k = hf * 64 + kk;
            a = fmaf(sn[k], G1[k * 16], a);
        }
        shp[n][hf][cc] = a;
    }
    __syncthreads();
    if (t2 < 16) {
        float a = shp[n][0][t2] + shp[n][1][t2];
        sh[n][t2] = a / (1.0f + expf(-a));
    }
    __syncthreads();

    if (t2 < 128) {
        const float* G2 = Wg2 + layer * 16 * FF;
        float gate = 0.f;
#pragma unroll
        for (int j = 0; j < 16; j++) gate = fmaf(sh[n][j], G2[j * FF + t2], gate);
        float w = gate * Wvout[layer * FF + t2];
        const float* sn = sred + n * 512;
        float m0 = sn[FF + t2] * w;
        float m1 = sn[2 * FF + t2] * w;
        float m2 = sn[3 * FF + t2] * w;
#pragma unroll
        for (int off = 16; off > 0; off >>= 1) {
            m0 += __shfl_down_sync(0xffffffffu, m0, off);
            m1 += __shfl_down_sync(0xffffffffu, m1, off);
            m2 += __shfl_down_sync(0xffffffffu, m2, off);
        }
        if ((t2 & 31) == 0) {
            int wp = t2 >> 5;
            rb[n][0][wp] = m0; rb[n][1][wp] = m1; rb[n][2][wp] = m2;
        }
    }
    __syncthreads();
    if (t2 < 3) {
        float pnew = sp[(r0 + n) * 3 + t2]
                   + rb[n][t2][0] + rb[n][t2][1] + rb[n][t2][2] + rb[n][t2][3];
        g_posbuf[1 - p][bn * 3 + t2] = pnew;
        if (layer == LL - 1)
            out[bn * 3 + t2] = pnew - pos_in[bn * 3 + t2];
    }

    if (layer + 1 < LL) {
        const float* W = Wnode + (layer + 1) * FF * FF + c4;
        const float* sn = sred + n * 512;
        float4 zacc = make_float4(0.f, 0.f, 0.f, 0.f);
#pragma unroll
        for (int kk = 0; kk < 16; kk++) {
            int k = q8 * 16 + kk;
            float4 w4 = *(const float4*)(W + k * FF);
            float s = sn[k];
            zacc.x = fmaf(s, w4.x, zacc.x); zacc.y = fmaf(s, w4.y, zacc.y);
            zacc.z = fmaf(s, w4.z, zacc.z); zacc.w = fmaf(s, w4.w, zacc.w);
        }
        __syncthreads();
        *(float4*)&rp[q8 * 1024 + n * 512 + c4] = zacc;
        __syncthreads();
        if (t2 < 128) {
            float s = 0.f;
#pragma unroll
            for (int qq = 0; qq < 8; qq++) s += rp[qq * 1024 + n * 512 + t2];
            zred[n][t2] = s;
        }
        __syncthreads();
    }

    if (t2 < 128) {
        const float* sn = sred + n * 512;
        float zn = (layer + 1 < LL) ? zred[n][t2] : 0.f;
        g_veczbuf[1 - p][bn * FF + t2] =
            make_uint2(pack2(sn[FF + t2], sn[2 * FF + t2]), pack2(sn[3 * FF + t2], zn));
    }
}

// ---------------------------------------------------------------------------
extern "C" void kernel_launch(void* const* d_in, const int* in_sizes, int n_in,
                              void* d_out, int out_size) {
    const float* positions     = (const float*)d_in[0];
    const int*   node_features = (const int*)d_in[1];
    const float* gf            = (const float*)d_in[2];
    const float* W_embed       = (const float*)d_in[3];
    const float* b_embed       = (const float*)d_in[4];
    const float* Wr1           = (const float*)d_in[5];
    const float* br1           = (const float*)d_in[6];
    const float* Wr2           = (const float*)d_in[7];
    const float* Wnode         = (const float*)d_in[8];
    const float* c1w           = (const float*)d_in[9];
    const float* c2w           = (const float*)d_in[10];
    const float* c3w           = (const float*)d_in[11];
    const float* Wmix0         = (const float*)d_in[12];
    const float* Wmix1         = (const float*)d_in[13];
    const float* Wg1           = (const float*)d_in[14];
    const float* Wg2           = (const float*)d_in[15];
    const float* Wvout         = (const float*)d_in[16];
    float* out = (float*)d_out;

    k_prep<<<TBLK * LL + BB * NN / 4, 512>>>(Wr1, br1, Wr2, positions, node_features,
                                             gf, W_embed, b_embed, Wnode);
    for (int i = 0; i < LL; i++)
        k_layer<<<dim3(NN / 2, BB), dim3(128, 4)>>>(positions, c1w, c2w, c3w,
                                                    Wmix0, Wmix1, Wg1, Wg2, Wvout,
                                                    Wnode, out, i);
}